// round 4
// baseline (speedup 1.0000x reference)
#include <cuda_runtime.h>
#include <cuda_bf16.h>
#include <math.h>
#include <stdint.h>

#define BATCH 8192
#define DIM 256
#define KCAT 768                      // [hi | hi | lo] / [hi | lo | hi]

// GEMM tiling
#define TM 256
#define TN 128
#define KC 32                         // bf16 per K stage
#define NCHUNK (KCAT / KC)            // 24
#define ROWPITCH 80                   // bytes per smem row (32 bf16 = 64B, pad to 80)
#define STAGE_BYTES ((TM + TN) * ROWPITCH)   // 30720
#define NSTAGES 3
#define SMEM_TOTAL (STAGE_BYTES * NSTAGES)   // 92160

#define NCTILE (BATCH / 64)           // 128 column tiles of 64 (per-warp col range)
#define NRSUB  (BATCH / 64)           // 128 row subtiles of 64 (per-warp row range)

// Row partial: (m, s, top4 vals, top4 col indices) -> 48B aligned
struct __align__(16) RP { float4 p0; float4 p1; int2 p2; };

// Scratch (device globals: allocation-free per harness rules)
static __device__ __nv_bfloat16 g_Acat[(size_t)BATCH * KCAT];
static __device__ __nv_bfloat16 g_Bcat[(size_t)BATCH * KCAT];
static __device__ RP     g_rp[BATCH][NCTILE];          // 48 MB
static __device__ float2 g_cp[NRSUB][BATCH];           // 8 MB
static __device__ float  g_diag[BATCH];
static __device__ float  g_rowlse[BATCH];
static __device__ float  g_cm[BATCH];
static __device__ float  g_cs[BATCH];
static __device__ long long g_corr[BATCH];
static __device__ float  g_hard_val[BATCH * 4];
static __device__ int    g_hard_idx[BATCH * 4];

// ---------------------------------------------------------------------------
// helpers
// ---------------------------------------------------------------------------
__device__ __forceinline__ uint32_t smem_to_u32(const void* p) {
    uint32_t a;
    asm("{ .reg .u64 t; cvta.to.shared.u64 t, %1; cvt.u32.u64 %0, t; }"
        : "=r"(a) : "l"(p));
    return a;
}
__device__ __forceinline__ void cp_async16(uint32_t smem_addr, const void* gptr) {
    asm volatile("cp.async.cg.shared.global [%0], [%1], 16;"
        :: "r"(smem_addr), "l"(gptr));
}
#define CP_COMMIT() asm volatile("cp.async.commit_group;" ::: "memory")
#define CP_WAIT1()  asm volatile("cp.async.wait_group 1;" ::: "memory")

__device__ __forceinline__ void ldsm_x4(uint32_t& r0, uint32_t& r1,
                                        uint32_t& r2, uint32_t& r3, uint32_t addr) {
    asm volatile("ldmatrix.sync.aligned.m8n8.x4.shared.b16 {%0,%1,%2,%3}, [%4];"
                 : "=r"(r0), "=r"(r1), "=r"(r2), "=r"(r3) : "r"(addr));
}
__device__ __forceinline__ void mma_bf16(float* d, const uint32_t* a, const uint32_t* b) {
    asm volatile(
        "mma.sync.aligned.m16n8k16.row.col.f32.bf16.bf16.f32 "
        "{%0,%1,%2,%3}, {%4,%5,%6,%7}, {%8,%9}, {%0,%1,%2,%3};"
        : "+f"(d[0]), "+f"(d[1]), "+f"(d[2]), "+f"(d[3])
        : "r"(a[0]), "r"(a[1]), "r"(a[2]), "r"(a[3]), "r"(b[0]), "r"(b[1]));
}

// top-4 insert tracking (value, index), descending
__device__ __forceinline__ void top4i(float v, int i,
                                      float& v0, int& i0, float& v1, int& i1,
                                      float& v2, int& i2, float& v3, int& i3)
{
    if (v > v3) {
        if (v > v0)      { v3=v2;i3=i2; v2=v1;i2=i1; v1=v0;i1=i0; v0=v;i0=i; }
        else if (v > v1) { v3=v2;i3=i2; v2=v1;i2=i1; v1=v;i1=i; }
        else if (v > v2) { v3=v2;i3=i2; v2=v;i2=i; }
        else             { v3=v;i3=i; }
    }
}
// merge (m, s) pairs for LSE
__device__ __forceinline__ void ms_merge(float& m, float& s, float om, float os)
{
    if (om > m) { s = s * __expf(m - om) + os; m = om; }
    else        { s += os * __expf(om - m); }
}

// ---------------------------------------------------------------------------
// K0: bf16 split precompute.  A_cat = [hi, hi, lo],  B_cat = [hi, lo, hi]
// sim = A_cat @ B_cat^T = hi*hi + hi*lo + lo*hi  (drops only lo*lo ~ 2^-18)
// ---------------------------------------------------------------------------
__global__ __launch_bounds__(256) void split_kernel(const float* __restrict__ V,
                                                    const float* __restrict__ Tm)
{
    size_t idx = (size_t)blockIdx.x * 256 + threadIdx.x;
    if (idx >= (size_t)BATCH * DIM) return;
    size_t row = idx / DIM;
    size_t k = idx % DIM;

    float a = V[idx];
    __nv_bfloat16 ah = __float2bfloat16(a);
    __nv_bfloat16 al = __float2bfloat16(a - __bfloat162float(ah));
    __nv_bfloat16* Ar = g_Acat + row * KCAT;
    Ar[k] = ah; Ar[k + 256] = ah; Ar[k + 512] = al;

    float b = Tm[idx];
    __nv_bfloat16 bh = __float2bfloat16(b);
    __nv_bfloat16 bl = __float2bfloat16(b - __bfloat162float(bh));
    __nv_bfloat16* Br = g_Bcat + row * KCAT;
    Br[k] = bh; Br[k + 256] = bl; Br[k + 512] = bh;
}

// ---------------------------------------------------------------------------
// K1: HMMA GEMM with FUSED row/col LSE + top-4 epilogue. CTA tile 256x128,
// 8 warps of 64x64, 3-stage cp.async pipeline, K = 768. No sim materialized.
// ---------------------------------------------------------------------------
__global__ __launch_bounds__(256, 1) void mma_gemm_kernel()
{
    extern __shared__ char smem[];
    const uint32_t smem_base = smem_to_u32(smem);
    const int tid = threadIdx.x;
    const int wid = tid >> 5;
    const int lane = tid & 31;
    const int m0 = blockIdx.y * TM;
    const int n0 = blockIdx.x * TN;

    const int wm = (wid & 3) * 64;   // warp row offset in tile
    const int wn = (wid >> 2) * 64;  // warp col offset in tile

    const char* Ag = (const char*)g_Acat;
    const char* Bg = (const char*)g_Bcat;

    auto load_stage = [&](int s) {
        const uint32_t sb = smem_base + (uint32_t)(s % NSTAGES) * STAGE_BYTES;
        const int kelem = s * KC;
        #pragma unroll
        for (int j = 0; j < 6; j++) {
            int c = tid + j * 256;                 // 0..1535
            if (c < 1024) {
                int row = c >> 2, q = c & 3;
                cp_async16(sb + row * ROWPITCH + q * 16,
                           Ag + ((size_t)(m0 + row) * KCAT + kelem + q * 8) * 2);
            } else {
                int c2 = c - 1024;
                int row = c2 >> 2, q = c2 & 3;
                cp_async16(sb + (TM + row) * ROWPITCH + q * 16,
                           Bg + ((size_t)(n0 + row) * KCAT + kelem + q * 8) * 2);
            }
        }
        CP_COMMIT();
    };

    float acc[4][8][4];
    #pragma unroll
    for (int mt = 0; mt < 4; mt++)
        #pragma unroll
        for (int nt = 0; nt < 8; nt++)
            #pragma unroll
            for (int e = 0; e < 4; e++) acc[mt][nt][e] = 0.f;

    load_stage(0);
    load_stage(1);

    for (int s = 0; s < NCHUNK; s++) {
        CP_WAIT1();
        __syncthreads();
        if (s + 2 < NCHUNK) load_stage(s + 2);

        const uint32_t sb = smem_base + (uint32_t)(s % NSTAGES) * STAGE_BYTES;
        const uint32_t Asb = sb;
        const uint32_t Bsb = sb + TM * ROWPITCH;

        #pragma unroll
        for (int ks = 0; ks < 2; ks++) {
            const int kb = ks * 32;
            uint32_t a[4][4], b[8][2];
            #pragma unroll
            for (int mt = 0; mt < 4; mt++) {
                uint32_t addr = Asb + (wm + mt * 16 + (lane & 15)) * ROWPITCH
                              + kb + (lane >> 4) * 16;
                ldsm_x4(a[mt][0], a[mt][1], a[mt][2], a[mt][3], addr);
            }
            #pragma unroll
            for (int np = 0; np < 4; np++) {
                int n = wn + np * 16 + (lane & 7) + ((lane >> 4) << 3);
                uint32_t addr = Bsb + n * ROWPITCH + kb + (((lane >> 3) & 1) << 4);
                ldsm_x4(b[np * 2][0], b[np * 2][1], b[np * 2 + 1][0], b[np * 2 + 1][1], addr);
            }
            #pragma unroll
            for (int mt = 0; mt < 4; mt++)
                #pragma unroll
                for (int nt = 0; nt < 8; nt++)
                    mma_bf16(acc[mt][nt], a[mt], b[nt]);
        }
        __syncthreads();
    }

    // ======================= FUSED EPILOGUE =======================
    // Fragment mapping: row = m0+wm+mt*16+(lane>>2)+h*8,
    //                   col = n0+wn+nt*8+(lane&3)*2+e, value acc[mt][nt][h*2+e]
    const float inv_t = 1.0f / 0.07f;
    const int lr = lane >> 2;
    const int lc = lane & 3;
    const int ctile = blockIdx.x * 2 + (wid >> 2);
    const int rsub  = blockIdx.y * 4 + (wid & 3);

    // ---- column partials: per-thread 16 cols x 8 row-values, shfl over lr ----
    {
        float cm[16], cs[16];
        #pragma unroll
        for (int c = 0; c < 16; c++) {
            int nt = c >> 1, e = c & 1;
            float mx = -3e38f;
            #pragma unroll
            for (int mt = 0; mt < 4; mt++) {
                mx = fmaxf(mx, acc[mt][nt][e]);
                mx = fmaxf(mx, acc[mt][nt][2 + e]);
            }
            mx *= inv_t;
            float sum = 0.f;
            #pragma unroll
            for (int mt = 0; mt < 4; mt++) {
                sum += __expf(acc[mt][nt][e] * inv_t - mx);
                sum += __expf(acc[mt][nt][2 + e] * inv_t - mx);
            }
            cm[c] = mx; cs[c] = sum;
        }
        #pragma unroll
        for (int d = 4; d <= 16; d <<= 1) {
            #pragma unroll
            for (int c = 0; c < 16; c++) {
                float om = __shfl_xor_sync(0xFFFFFFFFu, cm[c], d);
                float os = __shfl_xor_sync(0xFFFFFFFFu, cs[c], d);
                ms_merge(cm[c], cs[c], om, os);
            }
        }
        if (lr == 0) {
            #pragma unroll
            for (int c = 0; c < 16; c++) {
                int col = n0 + wn + (c >> 1) * 8 + lc * 2 + (c & 1);
                g_cp[rsub][col] = make_float2(cm[c], cs[c]);
            }
        }
    }

    // ---- row partials: per (mt,h) row, shfl over lc ----
    #pragma unroll
    for (int mt = 0; mt < 4; mt++) {
        #pragma unroll
        for (int h = 0; h < 2; h++) {
            const int row = m0 + wm + mt * 16 + lr + h * 8;
            float x[16];
            #pragma unroll
            for (int nt = 0; nt < 8; nt++) {
                x[nt * 2]     = acc[mt][nt][h * 2]     * inv_t;
                x[nt * 2 + 1] = acc[mt][nt][h * 2 + 1] * inv_t;
            }
            float rm = -3e38f;
            #pragma unroll
            for (int c = 0; c < 16; c++) rm = fmaxf(rm, x[c]);
            float rs = 0.f;
            #pragma unroll
            for (int c = 0; c < 16; c++) rs += __expf(x[c] - rm);

            float v0 = -3e38f, v1 = -3e38f, v2 = -3e38f, v3 = -3e38f;
            int i0 = 0, i1 = 0, i2 = 0, i3 = 0;
            #pragma unroll
            for (int c = 0; c < 16; c++) {
                int col = n0 + wn + (c >> 1) * 8 + lc * 2 + (c & 1);
                if (col == row) { g_diag[row] = x[c]; }
                else top4i(x[c], col, v0, i0, v1, i1, v2, i2, v3, i3);
            }
            #pragma unroll
            for (int d = 1; d <= 2; d <<= 1) {
                float om = __shfl_xor_sync(0xFFFFFFFFu, rm, d);
                float os = __shfl_xor_sync(0xFFFFFFFFu, rs, d);
                ms_merge(rm, rs, om, os);
                float ov[4]; int oi[4];
                ov[0] = __shfl_xor_sync(0xFFFFFFFFu, v0, d);
                ov[1] = __shfl_xor_sync(0xFFFFFFFFu, v1, d);
                ov[2] = __shfl_xor_sync(0xFFFFFFFFu, v2, d);
                ov[3] = __shfl_xor_sync(0xFFFFFFFFu, v3, d);
                oi[0] = __shfl_xor_sync(0xFFFFFFFFu, i0, d);
                oi[1] = __shfl_xor_sync(0xFFFFFFFFu, i1, d);
                oi[2] = __shfl_xor_sync(0xFFFFFFFFu, i2, d);
                oi[3] = __shfl_xor_sync(0xFFFFFFFFu, i3, d);
                #pragma unroll
                for (int k = 0; k < 4; k++)
                    top4i(ov[k], oi[k], v0, i0, v1, i1, v2, i2, v3, i3);
            }
            if (lc == 0) {
                RP* p = &g_rp[row][ctile];
                p->p0 = make_float4(rm, rs, v0, v1);
                p->p1 = make_float4(v2, v3, __int_as_float(i0), __int_as_float(i1));
                p->p2 = make_int2(i2, i3);
            }
        }
    }
}

// ---------------------------------------------------------------------------
// K2: per-row merge of 128 partials -> weighted rowLSE + hard pairs
// ---------------------------------------------------------------------------
__global__ __launch_bounds__(128) void rowmerge_kernel()
{
    __shared__ float sm[128], ss[128];
    __shared__ float sv0[128], sv1[128], sv2[128], sv3[128];
    __shared__ int   si0[128], si1[128], si2[128], si3[128];
    const int row = blockIdx.x;
    const int t = threadIdx.x;

    RP p = g_rp[row][t];
    sm[t] = p.p0.x; ss[t] = p.p0.y;
    sv0[t] = p.p0.z; sv1[t] = p.p0.w; sv2[t] = p.p1.x; sv3[t] = p.p1.y;
    si0[t] = __float_as_int(p.p1.z); si1[t] = __float_as_int(p.p1.w);
    si2[t] = p.p2.x; si3[t] = p.p2.y;
    __syncthreads();

    for (int s2 = 64; s2 > 0; s2 >>= 1) {
        if (t < s2) {
            float m = sm[t], s = ss[t];
            ms_merge(m, s, sm[t + s2], ss[t + s2]);
            sm[t] = m; ss[t] = s;
            float v0 = sv0[t], v1 = sv1[t], v2 = sv2[t], v3 = sv3[t];
            int i0 = si0[t], i1 = si1[t], i2 = si2[t], i3 = si3[t];
            top4i(sv0[t + s2], si0[t + s2], v0, i0, v1, i1, v2, i2, v3, i3);
            top4i(sv1[t + s2], si1[t + s2], v0, i0, v1, i1, v2, i2, v3, i3);
            top4i(sv2[t + s2], si2[t + s2], v0, i0, v1, i1, v2, i2, v3, i3);
            top4i(sv3[t + s2], si3[t + s2], v0, i0, v1, i1, v2, i2, v3, i3);
            sv0[t] = v0; sv1[t] = v1; sv2[t] = v2; sv3[t] = v3;
            si0[t] = i0; si1[t] = i1; si2[t] = i2; si3[t] = i3;
        }
        __syncthreads();
    }

    if (t == 0) {
        float M = sm[0], S = ss[0];
        float tv[4] = { sv0[0], sv1[0], sv2[0], sv3[0] };
        int   ti[4] = { si0[0], si1[0], si2[0], si3[0] };
        float Mw = fmaxf(M, 2.0f * tv[0]);
        float Sw = S * expf(M - Mw);
        #pragma unroll
        for (int k = 0; k < 4; k++)
            Sw += expf(2.0f * tv[k] - Mw) - expf(tv[k] - Mw);
        g_rowlse[row] = Mw + logf(Sw);
        #pragma unroll
        for (int k = 0; k < 4; k++) {
            g_hard_val[row * 4 + k] = tv[k];
            g_hard_idx[row * 4 + k] = ti[k];
        }
    }
}

// ---------------------------------------------------------------------------
// K3: per-column merge of 128 partials -> unweighted (M, S); zero corr
// ---------------------------------------------------------------------------
__global__ __launch_bounds__(256) void colmerge_kernel()
{
    const int col = blockIdx.x * 256 + threadIdx.x;
    float m = -3e38f, s = 0.f;
    for (int r = 0; r < NRSUB; r++) {
        float2 p = g_cp[r][col];
        ms_merge(m, s, p.x, p.y);
    }
    g_cm[col] = m;
    g_cs[col] = s;
    g_corr[col] = 0;
}

// ---------------------------------------------------------------------------
// K3b: apply hard-negative column corrections (fixed-point int64, deterministic)
// ---------------------------------------------------------------------------
__global__ __launch_bounds__(256) void colfix_kernel()
{
    const int t = blockIdx.x * 256 + threadIdx.x;   // 0..32767
    float x = g_hard_val[t];
    int j = g_hard_idx[t];
    float M = g_cm[j];
    float delta = expf(2.0f * x - M) - expf(x - M);
    long long q = (long long)((double)delta * 1048576.0);
    atomicAdd((unsigned long long*)&g_corr[j], (unsigned long long)q);
}

// ---------------------------------------------------------------------------
// K4: loss = sum_i [(rowLSE_i - diag_i) + (colLSE_i - diag_i)] / (2B)
// ---------------------------------------------------------------------------
__global__ __launch_bounds__(256) void finalize_kernel(float* __restrict__ out)
{
    __shared__ float red[256];
    const int tid = threadIdx.x;
    float acc = 0.f;
    for (int i = tid; i < BATCH; i += 256) {
        float corr = (float)((double)g_corr[i] * (1.0 / 1048576.0));
        float collse = g_cm[i] + logf(g_cs[i] + corr);
        acc += (g_rowlse[i] - g_diag[i]) + (collse - g_diag[i]);
    }
    red[tid] = acc; __syncthreads();
    for (int s = 128; s > 0; s >>= 1) {
        if (tid < s) red[tid] += red[tid + s];
        __syncthreads();
    }
    if (tid == 0) out[0] = red[0] / (2.0f * (float)BATCH);
}

extern "C" void kernel_launch(void* const* d_in, const int* in_sizes, int n_in,
                              void* d_out, int out_size)
{
    (void)in_sizes; (void)n_in; (void)out_size;
    const float* V  = (const float*)d_in[0];   // vision_embed [8192, 256]
    const float* Tm = (const float*)d_in[1];   // text_embed   [8192, 256]
    float* out = (float*)d_out;

    cudaFuncSetAttribute(mma_gemm_kernel,
                         cudaFuncAttributeMaxDynamicSharedMemorySize, SMEM_TOTAL);

    split_kernel<<<(BATCH * DIM + 255) / 256, 256>>>(V, Tm);
    mma_gemm_kernel<<<dim3(BATCH / TN, BATCH / TM), 256, SMEM_TOTAL>>>();
    rowmerge_kernel<<<BATCH, 128>>>();
    colmerge_kernel<<<BATCH / 256, 256>>>();
    colfix_kernel<<<(BATCH * 4) / 256, 256>>>();
    finalize_kernel<<<1, 256>>>(out);
}

// round 6
// speedup vs baseline: 1.3710x; 1.3710x over previous
#include <cuda_runtime.h>
#include <cuda_bf16.h>
#include <math.h>
#include <stdint.h>

#define BATCH 8192
#define DIM 256
#define KCAT 768                      // [hi | hi | lo] / [hi | lo | hi]

// GEMM tiling
#define TM 256
#define TN 128
#define KC 32                         // bf16 per K stage
#define NCHUNK (KCAT / KC)            // 24
#define ROWPITCH 80                   // bytes per smem row (32 bf16 = 64B, pad to 80)
#define STAGE_BYTES ((TM + TN) * ROWPITCH)   // 30720
#define NSTAGES 3
#define SMEM_TOTAL (STAGE_BYTES * NSTAGES)   // 92160

#define NCTILE (BATCH / 64)           // 128 column tiles of 64 (per-warp col range)
#define NRSUB  (BATCH / 64)           // 128 row bands of 64 (per-warp row range)

#define CORR_SCALE 524288.0           // 2^19 fixed-point for column corrections

// Row partial: sum + top4 (vals, idx). 48B.
struct __align__(16) RP { float4 a; float4 b; int4 c; };
// a = (sum, v0, v1, v2); b = (v3, bits(i0), bits(i1), bits(i2)); c.x = i3

// Scratch (device globals: allocation-free per harness rules)
static __device__ __nv_bfloat16 g_Acat[(size_t)BATCH * KCAT];
static __device__ __nv_bfloat16 g_Bcat[(size_t)BATCH * KCAT];
static __device__ RP    g_rp[BATCH][NCTILE];          // 48 MB
static __device__ float g_cp[NRSUB][BATCH];           // 4 MB (plain col sums)
static __device__ float g_diag[BATCH];
static __device__ float g_rowlse[BATCH];
static __device__ float g_cs[BATCH];
static __device__ long long g_corr[BATCH];
static __device__ float g_hard_val[BATCH * 4];
static __device__ int   g_hard_idx[BATCH * 4];

// ---------------------------------------------------------------------------
// helpers
// ---------------------------------------------------------------------------
__device__ __forceinline__ uint32_t smem_to_u32(const void* p) {
    uint32_t a;
    asm("{ .reg .u64 t; cvta.to.shared.u64 t, %1; cvt.u32.u64 %0, t; }"
        : "=r"(a) : "l"(p));
    return a;
}
__device__ __forceinline__ void cp_async16(uint32_t smem_addr, const void* gptr) {
    asm volatile("cp.async.cg.shared.global [%0], [%1], 16;"
        :: "r"(smem_addr), "l"(gptr));
}
#define CP_COMMIT() asm volatile("cp.async.commit_group;" ::: "memory")
#define CP_WAIT1()  asm volatile("cp.async.wait_group 1;" ::: "memory")

__device__ __forceinline__ void ldsm_x4(uint32_t& r0, uint32_t& r1,
                                        uint32_t& r2, uint32_t& r3, uint32_t addr) {
    asm volatile("ldmatrix.sync.aligned.m8n8.x4.shared.b16 {%0,%1,%2,%3}, [%4];"
                 : "=r"(r0), "=r"(r1), "=r"(r2), "=r"(r3) : "r"(addr));
}
__device__ __forceinline__ void mma_bf16(float* d, const uint32_t* a, const uint32_t* b) {
    asm volatile(
        "mma.sync.aligned.m16n8k16.row.col.f32.bf16.bf16.f32 "
        "{%0,%1,%2,%3}, {%4,%5,%6,%7}, {%8,%9}, {%0,%1,%2,%3};"
        : "+f"(d[0]), "+f"(d[1]), "+f"(d[2]), "+f"(d[3])
        : "r"(a[0]), "r"(a[1]), "r"(a[2]), "r"(a[3]), "r"(b[0]), "r"(b[1]));
}

// top-4 insert tracking (value, index), descending
__device__ __forceinline__ void top4i(float v, int i,
                                      float& v0, int& i0, float& v1, int& i1,
                                      float& v2, int& i2, float& v3, int& i3)
{
    if (v > v3) {
        if (v > v0)      { v3=v2;i3=i2; v2=v1;i2=i1; v1=v0;i1=i0; v0=v;i0=i; }
        else if (v > v1) { v3=v2;i3=i2; v2=v1;i2=i1; v1=v;i1=i; }
        else if (v > v2) { v3=v2;i3=i2; v2=v;i2=i; }
        else             { v3=v;i3=i; }
    }
}

// ---------------------------------------------------------------------------
// K0: bf16 split precompute.  A_cat = [hi, hi, lo],  B_cat = [hi, lo, hi]
// ---------------------------------------------------------------------------
__global__ __launch_bounds__(256) void split_kernel(const float* __restrict__ V,
                                                    const float* __restrict__ Tm)
{
    size_t idx = (size_t)blockIdx.x * 256 + threadIdx.x;
    if (idx >= (size_t)BATCH * DIM) return;
    size_t row = idx / DIM;
    size_t k = idx % DIM;

    float a = V[idx];
    __nv_bfloat16 ah = __float2bfloat16(a);
    __nv_bfloat16 al = __float2bfloat16(a - __bfloat162float(ah));
    __nv_bfloat16* Ar = g_Acat + row * KCAT;
    Ar[k] = ah; Ar[k + 256] = ah; Ar[k + 512] = al;

    float b = Tm[idx];
    __nv_bfloat16 bh = __float2bfloat16(b);
    __nv_bfloat16 bl = __float2bfloat16(b - __bfloat162float(bh));
    __nv_bfloat16* Br = g_Bcat + row * KCAT;
    Br[k] = bh; Br[k + 256] = bl; Br[k + 512] = bh;
}

// ---------------------------------------------------------------------------
// K1: HMMA GEMM, fused minimal epilogue: per-warp row partial (sum, top4)
// and column partial (sum). No max-tracking (bounded logits), exp reused.
// ---------------------------------------------------------------------------
__global__ __launch_bounds__(256, 1) void mma_gemm_kernel()
{
    extern __shared__ char smem[];
    const uint32_t smem_base = smem_to_u32(smem);
    const int tid = threadIdx.x;
    const int wid = tid >> 5;
    const int lane = tid & 31;
    const int m0 = blockIdx.y * TM;
    const int n0 = blockIdx.x * TN;

    const int wm = (wid & 3) * 64;   // warp row offset in tile
    const int wn = (wid >> 2) * 64;  // warp col offset in tile

    const char* Ag = (const char*)g_Acat;
    const char* Bg = (const char*)g_Bcat;

    auto load_stage = [&](int s) {
        const uint32_t sb = smem_base + (uint32_t)(s % NSTAGES) * STAGE_BYTES;
        const int kelem = s * KC;
        #pragma unroll
        for (int j = 0; j < 6; j++) {
            int c = tid + j * 256;
            if (c < 1024) {
                int row = c >> 2, q = c & 3;
                cp_async16(sb + row * ROWPITCH + q * 16,
                           Ag + ((size_t)(m0 + row) * KCAT + kelem + q * 8) * 2);
            } else {
                int c2 = c - 1024;
                int row = c2 >> 2, q = c2 & 3;
                cp_async16(sb + (TM + row) * ROWPITCH + q * 16,
                           Bg + ((size_t)(n0 + row) * KCAT + kelem + q * 8) * 2);
            }
        }
        CP_COMMIT();
    };

    float acc[4][8][4];
    #pragma unroll
    for (int mt = 0; mt < 4; mt++)
        #pragma unroll
        for (int nt = 0; nt < 8; nt++)
            #pragma unroll
            for (int e = 0; e < 4; e++) acc[mt][nt][e] = 0.f;

    load_stage(0);
    load_stage(1);

    for (int s = 0; s < NCHUNK; s++) {
        CP_WAIT1();
        __syncthreads();
        if (s + 2 < NCHUNK) load_stage(s + 2);

        const uint32_t sb = smem_base + (uint32_t)(s % NSTAGES) * STAGE_BYTES;
        const uint32_t Asb = sb;
        const uint32_t Bsb = sb + TM * ROWPITCH;

        #pragma unroll
        for (int ks = 0; ks < 2; ks++) {
            const int kb = ks * 32;
            uint32_t a[4][4], b[8][2];
            #pragma unroll
            for (int mt = 0; mt < 4; mt++) {
                uint32_t addr = Asb + (wm + mt * 16 + (lane & 15)) * ROWPITCH
                              + kb + (lane >> 4) * 16;
                ldsm_x4(a[mt][0], a[mt][1], a[mt][2], a[mt][3], addr);
            }
            #pragma unroll
            for (int np = 0; np < 4; np++) {
                int n = wn + np * 16 + (lane & 7) + ((lane >> 4) << 3);
                uint32_t addr = Bsb + n * ROWPITCH + kb + (((lane >> 3) & 1) << 4);
                ldsm_x4(b[np * 2][0], b[np * 2][1], b[np * 2 + 1][0], b[np * 2 + 1][1], addr);
            }
            #pragma unroll
            for (int mt = 0; mt < 4; mt++)
                #pragma unroll
                for (int nt = 0; nt < 8; nt++)
                    mma_bf16(acc[mt][nt], a[mt], b[nt]);
        }
        __syncthreads();
    }

    // ======================= FUSED EPILOGUE =======================
    // row = m0+wm+mt*16+(lane>>2)+h*8; col = n0+wn+nt*8+(lane&3)*2+e;
    // value = acc[mt][nt][h*2+e]
    const float inv_t = 1.0f / 0.07f;
    const int lr = lane >> 2;
    const int lc = lane & 3;
    const int ctile = blockIdx.x * 2 + (wid >> 2);
    const int rsub  = blockIdx.y * 4 + (wid & 3);

    float cs[16];
    #pragma unroll
    for (int c = 0; c < 16; c++) cs[c] = 0.f;

    #pragma unroll
    for (int mt = 0; mt < 4; mt++) {
        #pragma unroll
        for (int h = 0; h < 2; h++) {
            const int row = m0 + wm + mt * 16 + lr + h * 8;
            float rsum = 0.f;
            float v0 = -3e38f, v1 = -3e38f, v2 = -3e38f, v3 = -3e38f;
            int i0 = 0, i1 = 0, i2 = 0, i3 = 0;
            #pragma unroll
            for (int nt = 0; nt < 8; nt++) {
                #pragma unroll
                for (int e = 0; e < 2; e++) {
                    const int col = n0 + wn + nt * 8 + lc * 2 + e;
                    float x = acc[mt][nt][h * 2 + e] * inv_t;
                    float ex = __expf(x);
                    rsum += ex;
                    cs[nt * 2 + e] += ex;
                    if (col != row)
                        top4i(x, col, v0, i0, v1, i1, v2, i2, v3, i3);
                }
            }
            // reduce over lc (lane bits 0..1) — SNAPSHOT before inserting!
            #pragma unroll
            for (int d = 1; d <= 2; d <<= 1) {
                rsum += __shfl_xor_sync(0xFFFFFFFFu, rsum, d);
                float ov0 = __shfl_xor_sync(0xFFFFFFFFu, v0, d);
                float ov1 = __shfl_xor_sync(0xFFFFFFFFu, v1, d);
                float ov2 = __shfl_xor_sync(0xFFFFFFFFu, v2, d);
                float ov3 = __shfl_xor_sync(0xFFFFFFFFu, v3, d);
                int   oj0 = __shfl_xor_sync(0xFFFFFFFFu, i0, d);
                int   oj1 = __shfl_xor_sync(0xFFFFFFFFu, i1, d);
                int   oj2 = __shfl_xor_sync(0xFFFFFFFFu, i2, d);
                int   oj3 = __shfl_xor_sync(0xFFFFFFFFu, i3, d);
                top4i(ov0, oj0, v0, i0, v1, i1, v2, i2, v3, i3);
                top4i(ov1, oj1, v0, i0, v1, i1, v2, i2, v3, i3);
                top4i(ov2, oj2, v0, i0, v1, i1, v2, i2, v3, i3);
                top4i(ov3, oj3, v0, i0, v1, i1, v2, i2, v3, i3);
            }
            if (lc == 0) {
                RP* p = &g_rp[row][ctile];
                p->a = make_float4(rsum, v0, v1, v2);
                p->b = make_float4(v3, __int_as_float(i0), __int_as_float(i1),
                                   __int_as_float(i2));
                p->c = make_int4(i3, 0, 0, 0);
            }
        }
    }

    // column sums: reduce over lr (lane bits 2..4)
    #pragma unroll
    for (int d = 4; d <= 16; d <<= 1) {
        #pragma unroll
        for (int c = 0; c < 16; c++)
            cs[c] += __shfl_xor_sync(0xFFFFFFFFu, cs[c], d);
    }
    if (lr == 0) {
        #pragma unroll
        for (int c = 0; c < 16; c++) {
            int col = n0 + wn + (c >> 1) * 8 + lc * 2 + (c & 1);
            g_cp[rsub][col] = cs[c];
        }
    }
}

// ---------------------------------------------------------------------------
// K1b: exact fp32 diag: diag_i = dot(V_i, T_i)/T.  One warp per row.
// ---------------------------------------------------------------------------
__global__ __launch_bounds__(256) void diag_kernel(const float* __restrict__ V,
                                                   const float* __restrict__ Tm)
{
    const int row = blockIdx.x * 8 + (threadIdx.x >> 5);
    const int lane = threadIdx.x & 31;
    const float4* v = (const float4*)(V + (size_t)row * DIM);
    const float4* t = (const float4*)(Tm + (size_t)row * DIM);
    float s = 0.f;
    #pragma unroll
    for (int q = 0; q < 2; q++) {
        float4 a = v[lane + q * 32];
        float4 b = t[lane + q * 32];
        s += a.x * b.x + a.y * b.y + a.z * b.z + a.w * b.w;
    }
    #pragma unroll
    for (int d = 16; d > 0; d >>= 1) s += __shfl_xor_sync(0xFFFFFFFFu, s, d);
    if (lane == 0) g_diag[row] = s * (1.0f / 0.07f);
}

// ---------------------------------------------------------------------------
// K2: per-row merge of 128 partials (one warp per row) -> weighted rowLSE
// ---------------------------------------------------------------------------
__global__ __launch_bounds__(256) void rowmerge_kernel()
{
    const int row = blockIdx.x * 8 + (threadIdx.x >> 5);
    const int lane = threadIdx.x & 31;

    float S = 0.f;
    float v0 = -3e38f, v1 = -3e38f, v2 = -3e38f, v3 = -3e38f;
    int i0 = 0, i1 = 0, i2 = 0, i3 = 0;
    #pragma unroll
    for (int q = 0; q < 4; q++) {
        RP p = g_rp[row][lane + q * 32];
        S += p.a.x;
        top4i(p.a.y, __float_as_int(p.b.y), v0, i0, v1, i1, v2, i2, v3, i3);
        top4i(p.a.z, __float_as_int(p.b.z), v0, i0, v1, i1, v2, i2, v3, i3);
        top4i(p.a.w, __float_as_int(p.b.w), v0, i0, v1, i1, v2, i2, v3, i3);
        top4i(p.b.x, p.c.x,                 v0, i0, v1, i1, v2, i2, v3, i3);
    }
    #pragma unroll
    for (int d = 16; d > 0; d >>= 1) {
        S += __shfl_xor_sync(0xFFFFFFFFu, S, d);
        // SNAPSHOT all four before inserting (symmetric-merge hazard)
        float ov0 = __shfl_xor_sync(0xFFFFFFFFu, v0, d);
        float ov1 = __shfl_xor_sync(0xFFFFFFFFu, v1, d);
        float ov2 = __shfl_xor_sync(0xFFFFFFFFu, v2, d);
        float ov3 = __shfl_xor_sync(0xFFFFFFFFu, v3, d);
        int   oj0 = __shfl_xor_sync(0xFFFFFFFFu, i0, d);
        int   oj1 = __shfl_xor_sync(0xFFFFFFFFu, i1, d);
        int   oj2 = __shfl_xor_sync(0xFFFFFFFFu, i2, d);
        int   oj3 = __shfl_xor_sync(0xFFFFFFFFu, i3, d);
        top4i(ov0, oj0, v0, i0, v1, i1, v2, i2, v3, i3);
        top4i(ov1, oj1, v0, i0, v1, i1, v2, i2, v3, i3);
        top4i(ov2, oj2, v0, i0, v1, i1, v2, i2, v3, i3);
        top4i(ov3, oj3, v0, i0, v1, i1, v2, i2, v3, i3);
    }
    if (lane == 0) {
        float Sw = S + (expf(2.f * v0) - expf(v0)) + (expf(2.f * v1) - expf(v1))
                     + (expf(2.f * v2) - expf(v2)) + (expf(2.f * v3) - expf(v3));
        g_rowlse[row] = logf(Sw);
        g_hard_val[row * 4 + 0] = v0; g_hard_idx[row * 4 + 0] = i0;
        g_hard_val[row * 4 + 1] = v1; g_hard_idx[row * 4 + 1] = i1;
        g_hard_val[row * 4 + 2] = v2; g_hard_idx[row * 4 + 2] = i2;
        g_hard_val[row * 4 + 3] = v3; g_hard_idx[row * 4 + 3] = i3;
    }
}

// ---------------------------------------------------------------------------
// K3: per-column merge of 128 band sums; zero corr
// ---------------------------------------------------------------------------
__global__ __launch_bounds__(256) void colmerge_kernel()
{
    const int col = blockIdx.x * 256 + threadIdx.x;
    float s = 0.f;
    #pragma unroll 8
    for (int r = 0; r < NRSUB; r++) s += g_cp[r][col];
    g_cs[col] = s;
    g_corr[col] = 0;
}

// ---------------------------------------------------------------------------
// K3b: hard-negative column corrections (int64 fixed point, order-independent)
// ---------------------------------------------------------------------------
__global__ __launch_bounds__(256) void colfix_kernel()
{
    const int t = blockIdx.x * 256 + threadIdx.x;   // 0..32767
    float x = g_hard_val[t];
    int j = g_hard_idx[t];
    float delta = expf(2.0f * x) - expf(x);
    long long q = (long long)((double)delta * CORR_SCALE);
    atomicAdd((unsigned long long*)&g_corr[j], (unsigned long long)q);
}

// ---------------------------------------------------------------------------
// K4: loss = sum_i [(rowLSE_i - diag_i) + (colLSE_i - diag_i)] / (2B)
// ---------------------------------------------------------------------------
__global__ __launch_bounds__(256) void finalize_kernel(float* __restrict__ out)
{
    __shared__ float red[256];
    const int tid = threadIdx.x;
    float acc = 0.f;
    for (int i = tid; i < BATCH; i += 256) {
        float corr = (float)((double)g_corr[i] * (1.0 / CORR_SCALE));
        float collse = logf(g_cs[i] + corr);
        acc += (g_rowlse[i] - g_diag[i]) + (collse - g_diag[i]);
    }
    red[tid] = acc; __syncthreads();
    for (int s = 128; s > 0; s >>= 1) {
        if (tid < s) red[tid] += red[tid + s];
        __syncthreads();
    }
    if (tid == 0) out[0] = red[0] / (2.0f * (float)BATCH);
}

extern "C" void kernel_launch(void* const* d_in, const int* in_sizes, int n_in,
                              void* d_out, int out_size)
{
    (void)in_sizes; (void)n_in; (void)out_size;
    const float* V  = (const float*)d_in[0];   // vision_embed [8192, 256]
    const float* Tm = (const float*)d_in[1];   // text_embed   [8192, 256]
    float* out = (float*)d_out;

    cudaFuncSetAttribute(mma_gemm_kernel,
                         cudaFuncAttributeMaxDynamicSharedMemorySize, SMEM_TOTAL);

    split_kernel<<<(BATCH * DIM + 255) / 256, 256>>>(V, Tm);
    mma_gemm_kernel<<<dim3(BATCH / TN, BATCH / TM), 256, SMEM_TOTAL>>>();
    diag_kernel<<<BATCH / 8, 256>>>(V, Tm);
    rowmerge_kernel<<<BATCH / 8, 256>>>();
    colmerge_kernel<<<BATCH / 256, 256>>>();
    colfix_kernel<<<(BATCH * 4) / 256, 256>>>();
    finalize_kernel<<<1, 256>>>(out);
}

// round 7
// speedup vs baseline: 1.8562x; 1.3539x over previous
#include <cuda_runtime.h>
#include <cuda_bf16.h>
#include <math.h>
#include <stdint.h>

#define BATCH 8192
#define DIM 256
#define KCAT 768                      // [hi | hi | lo] / [hi | lo | hi]

// GEMM tiling: CTA 128x128, 8 warps of 32x64, 2 CTAs/SM
#define TM 128
#define TN 128
#define KC 32                         // bf16 per K stage
#define NCHUNK (KCAT / KC)            // 24
#define ROWPITCH 80                   // bytes per smem row (32 bf16 = 64B, pad to 80)
#define STAGE_BYTES ((TM + TN) * ROWPITCH)   // 20480
#define NSTAGES 3
#define SMEM_TOTAL (STAGE_BYTES * NSTAGES)   // 61440

#define NCTILE (BATCH / 64)           // 128 column tiles of 64 (per-warp col range)
#define NRSUB  (BATCH / 32)           // 256 row bands of 32 (per-warp row range)

#define CORR_SCALE 524288.0           // 2^19 fixed-point for column corrections

// Row partial: sum + top4 (vals, idx). 48B.
struct __align__(16) RP { float4 a; float4 b; int4 c; };
// a = (sum, v0, v1, v2); b = (v3, bits(i0), bits(i1), bits(i2)); c.x = i3

// Scratch (device globals: allocation-free per harness rules)
static __device__ __nv_bfloat16 g_Acat[(size_t)BATCH * KCAT];
static __device__ __nv_bfloat16 g_Bcat[(size_t)BATCH * KCAT];
static __device__ RP    g_rp[BATCH][NCTILE];          // 48 MB
static __device__ float g_cp[NRSUB][BATCH];           // 8 MB (plain col sums)
static __device__ float g_diag[BATCH];
static __device__ float g_rowlse[BATCH];
static __device__ float g_cs[BATCH];
static __device__ long long g_corr[BATCH];
static __device__ float g_hard_val[BATCH * 4];
static __device__ int   g_hard_idx[BATCH * 4];

// ---------------------------------------------------------------------------
// helpers
// ---------------------------------------------------------------------------
__device__ __forceinline__ uint32_t smem_to_u32(const void* p) {
    uint32_t a;
    asm("{ .reg .u64 t; cvta.to.shared.u64 t, %1; cvt.u32.u64 %0, t; }"
        : "=r"(a) : "l"(p));
    return a;
}
__device__ __forceinline__ void cp_async16(uint32_t smem_addr, const void* gptr) {
    asm volatile("cp.async.cg.shared.global [%0], [%1], 16;"
        :: "r"(smem_addr), "l"(gptr));
}
#define CP_COMMIT() asm volatile("cp.async.commit_group;" ::: "memory")
#define CP_WAIT1()  asm volatile("cp.async.wait_group 1;" ::: "memory")

__device__ __forceinline__ void ldsm_x4(uint32_t& r0, uint32_t& r1,
                                        uint32_t& r2, uint32_t& r3, uint32_t addr) {
    asm volatile("ldmatrix.sync.aligned.m8n8.x4.shared.b16 {%0,%1,%2,%3}, [%4];"
                 : "=r"(r0), "=r"(r1), "=r"(r2), "=r"(r3) : "r"(addr));
}
__device__ __forceinline__ void mma_bf16(float* d, const uint32_t* a, const uint32_t* b) {
    asm volatile(
        "mma.sync.aligned.m16n8k16.row.col.f32.bf16.bf16.f32 "
        "{%0,%1,%2,%3}, {%4,%5,%6,%7}, {%8,%9}, {%0,%1,%2,%3};"
        : "+f"(d[0]), "+f"(d[1]), "+f"(d[2]), "+f"(d[3])
        : "r"(a[0]), "r"(a[1]), "r"(a[2]), "r"(a[3]), "r"(b[0]), "r"(b[1]));
}

// top-4 insert tracking (value, index), descending
__device__ __forceinline__ void top4i(float v, int i,
                                      float& v0, int& i0, float& v1, int& i1,
                                      float& v2, int& i2, float& v3, int& i3)
{
    if (v > v3) {
        if (v > v0)      { v3=v2;i3=i2; v2=v1;i2=i1; v1=v0;i1=i0; v0=v;i0=i; }
        else if (v > v1) { v3=v2;i3=i2; v2=v1;i2=i1; v1=v;i1=i; }
        else if (v > v2) { v3=v2;i3=i2; v2=v;i2=i; }
        else             { v3=v;i3=i; }
    }
}

// ---------------------------------------------------------------------------
// K0: bf16 split precompute.  A_cat = [hi, hi, lo],  B_cat = [hi, lo, hi]
// ---------------------------------------------------------------------------
__global__ __launch_bounds__(256) void split_kernel(const float* __restrict__ V,
                                                    const float* __restrict__ Tm)
{
    size_t idx = (size_t)blockIdx.x * 256 + threadIdx.x;
    if (idx >= (size_t)BATCH * DIM) return;
    size_t row = idx / DIM;
    size_t k = idx % DIM;

    float a = V[idx];
    __nv_bfloat16 ah = __float2bfloat16(a);
    __nv_bfloat16 al = __float2bfloat16(a - __bfloat162float(ah));
    __nv_bfloat16* Ar = g_Acat + row * KCAT;
    Ar[k] = ah; Ar[k + 256] = ah; Ar[k + 512] = al;

    float b = Tm[idx];
    __nv_bfloat16 bh = __float2bfloat16(b);
    __nv_bfloat16 bl = __float2bfloat16(b - __bfloat162float(bh));
    __nv_bfloat16* Br = g_Bcat + row * KCAT;
    Br[k] = bh; Br[k + 256] = bl; Br[k + 512] = bh;
}

// ---------------------------------------------------------------------------
// K1: HMMA GEMM, fused epilogue (row sum+top4, col sums). 128x128 CTA tile,
// 8 warps of 32x64, 3-stage cp.async, 2 CTAs/SM.
// ---------------------------------------------------------------------------
__global__ __launch_bounds__(256, 2) void mma_gemm_kernel()
{
    extern __shared__ char smem[];
    const uint32_t smem_base = smem_to_u32(smem);
    const int tid = threadIdx.x;
    const int wid = tid >> 5;
    const int lane = tid & 31;
    const int m0 = blockIdx.y * TM;
    const int n0 = blockIdx.x * TN;

    const int wm = (wid & 3) * 32;   // warp row offset in tile
    const int wn = (wid >> 2) * 64;  // warp col offset in tile

    const char* Ag = (const char*)g_Acat;
    const char* Bg = (const char*)g_Bcat;

    // stage loader: A rows [m0,m0+128) then B rows [n0,n0+128), 16B chunks
    auto load_stage = [&](int s) {
        const uint32_t sb = smem_base + (uint32_t)(s % NSTAGES) * STAGE_BYTES;
        const int kelem = s * KC;
        #pragma unroll
        for (int j = 0; j < 4; j++) {
            int c = tid + j * 256;                 // 0..1023
            int row = c >> 2, q = c & 3;           // row 0..255, q 0..3
            if (row < TM) {
                cp_async16(sb + row * ROWPITCH + q * 16,
                           Ag + ((size_t)(m0 + row) * KCAT + kelem + q * 8) * 2);
            } else {
                cp_async16(sb + row * ROWPITCH + q * 16,
                           Bg + ((size_t)(n0 + row - TM) * KCAT + kelem + q * 8) * 2);
            }
        }
        CP_COMMIT();
    };

    float acc[2][8][4];
    #pragma unroll
    for (int mt = 0; mt < 2; mt++)
        #pragma unroll
        for (int nt = 0; nt < 8; nt++)
            #pragma unroll
            for (int e = 0; e < 4; e++) acc[mt][nt][e] = 0.f;

    load_stage(0);
    load_stage(1);

    for (int s = 0; s < NCHUNK; s++) {
        CP_WAIT1();
        __syncthreads();
        if (s + 2 < NCHUNK) load_stage(s + 2);

        const uint32_t sb = smem_base + (uint32_t)(s % NSTAGES) * STAGE_BYTES;
        const uint32_t Asb = sb;
        const uint32_t Bsb = sb + TM * ROWPITCH;

        #pragma unroll
        for (int ks = 0; ks < 2; ks++) {
            const int kb = ks * 32;
            uint32_t a[2][4], b[8][2];
            #pragma unroll
            for (int mt = 0; mt < 2; mt++) {
                uint32_t addr = Asb + (wm + mt * 16 + (lane & 15)) * ROWPITCH
                              + kb + (lane >> 4) * 16;
                ldsm_x4(a[mt][0], a[mt][1], a[mt][2], a[mt][3], addr);
            }
            #pragma unroll
            for (int np = 0; np < 4; np++) {
                int n = wn + np * 16 + (lane & 7) + ((lane >> 4) << 3);
                uint32_t addr = Bsb + n * ROWPITCH + kb + (((lane >> 3) & 1) << 4);
                ldsm_x4(b[np * 2][0], b[np * 2][1], b[np * 2 + 1][0], b[np * 2 + 1][1], addr);
            }
            #pragma unroll
            for (int mt = 0; mt < 2; mt++)
                #pragma unroll
                for (int nt = 0; nt < 8; nt++)
                    mma_bf16(acc[mt][nt], a[mt], b[nt]);
        }
        __syncthreads();
    }

    // ======================= FUSED EPILOGUE =======================
    // row = m0+wm+mt*16+(lane>>2)+h*8; col = n0+wn+nt*8+(lane&3)*2+e;
    // value = acc[mt][nt][h*2+e]
    const float inv_t = 1.0f / 0.07f;
    const int lr = lane >> 2;
    const int lc = lane & 3;
    const int ctile = blockIdx.x * 2 + (wid >> 2);   // 64-col tile index
    const int rsub  = blockIdx.y * 4 + (wid & 3);    // 32-row band index

    float cs[16];
    #pragma unroll
    for (int c = 0; c < 16; c++) cs[c] = 0.f;

    #pragma unroll
    for (int mt = 0; mt < 2; mt++) {
        #pragma unroll
        for (int h = 0; h < 2; h++) {
            const int row = m0 + wm + mt * 16 + lr + h * 8;
            float rsum = 0.f;
            float v0 = -3e38f, v1 = -3e38f, v2 = -3e38f, v3 = -3e38f;
            int i0 = 0, i1 = 0, i2 = 0, i3 = 0;
            #pragma unroll
            for (int nt = 0; nt < 8; nt++) {
                #pragma unroll
                for (int e = 0; e < 2; e++) {
                    const int col = n0 + wn + nt * 8 + lc * 2 + e;
                    float x = acc[mt][nt][h * 2 + e] * inv_t;
                    float ex = __expf(x);
                    rsum += ex;
                    cs[nt * 2 + e] += ex;
                    if (col != row)
                        top4i(x, col, v0, i0, v1, i1, v2, i2, v3, i3);
                }
            }
            // reduce over lc (lane bits 0..1) — snapshot before inserting
            #pragma unroll
            for (int d = 1; d <= 2; d <<= 1) {
                rsum += __shfl_xor_sync(0xFFFFFFFFu, rsum, d);
                float ov0 = __shfl_xor_sync(0xFFFFFFFFu, v0, d);
                float ov1 = __shfl_xor_sync(0xFFFFFFFFu, v1, d);
                float ov2 = __shfl_xor_sync(0xFFFFFFFFu, v2, d);
                float ov3 = __shfl_xor_sync(0xFFFFFFFFu, v3, d);
                int   oj0 = __shfl_xor_sync(0xFFFFFFFFu, i0, d);
                int   oj1 = __shfl_xor_sync(0xFFFFFFFFu, i1, d);
                int   oj2 = __shfl_xor_sync(0xFFFFFFFFu, i2, d);
                int   oj3 = __shfl_xor_sync(0xFFFFFFFFu, i3, d);
                top4i(ov0, oj0, v0, i0, v1, i1, v2, i2, v3, i3);
                top4i(ov1, oj1, v0, i0, v1, i1, v2, i2, v3, i3);
                top4i(ov2, oj2, v0, i0, v1, i1, v2, i2, v3, i3);
                top4i(ov3, oj3, v0, i0, v1, i1, v2, i2, v3, i3);
            }
            if (lc == 0) {
                RP* p = &g_rp[row][ctile];
                p->a = make_float4(rsum, v0, v1, v2);
                p->b = make_float4(v3, __int_as_float(i0), __int_as_float(i1),
                                   __int_as_float(i2));
                p->c = make_int4(i3, 0, 0, 0);
            }
        }
    }

    // column sums: reduce over lr (lane bits 2..4)
    #pragma unroll
    for (int d = 4; d <= 16; d <<= 1) {
        #pragma unroll
        for (int c = 0; c < 16; c++)
            cs[c] += __shfl_xor_sync(0xFFFFFFFFu, cs[c], d);
    }
    if (lr == 0) {
        #pragma unroll
        for (int c = 0; c < 16; c++) {
            int col = n0 + wn + (c >> 1) * 8 + lc * 2 + (c & 1);
            g_cp[rsub][col] = cs[c];
        }
    }
}

// ---------------------------------------------------------------------------
// K1b: exact fp32 diag: diag_i = dot(V_i, T_i)/T.  One warp per row.
// ---------------------------------------------------------------------------
__global__ __launch_bounds__(256) void diag_kernel(const float* __restrict__ V,
                                                   const float* __restrict__ Tm)
{
    const int row = blockIdx.x * 8 + (threadIdx.x >> 5);
    const int lane = threadIdx.x & 31;
    const float4* v = (const float4*)(V + (size_t)row * DIM);
    const float4* t = (const float4*)(Tm + (size_t)row * DIM);
    float s = 0.f;
    #pragma unroll
    for (int q = 0; q < 2; q++) {
        float4 a = v[lane + q * 32];
        float4 b = t[lane + q * 32];
        s += a.x * b.x + a.y * b.y + a.z * b.z + a.w * b.w;
    }
    #pragma unroll
    for (int d = 16; d > 0; d >>= 1) s += __shfl_xor_sync(0xFFFFFFFFu, s, d);
    if (lane == 0) g_diag[row] = s * (1.0f / 0.07f);
}

// ---------------------------------------------------------------------------
// K2: per-row merge of 128 partials (one warp per row) -> weighted rowLSE
// ---------------------------------------------------------------------------
__global__ __launch_bounds__(256) void rowmerge_kernel()
{
    const int row = blockIdx.x * 8 + (threadIdx.x >> 5);
    const int lane = threadIdx.x & 31;

    float S = 0.f;
    float v0 = -3e38f, v1 = -3e38f, v2 = -3e38f, v3 = -3e38f;
    int i0 = 0, i1 = 0, i2 = 0, i3 = 0;
    #pragma unroll
    for (int q = 0; q < 4; q++) {
        RP p = g_rp[row][lane + q * 32];
        S += p.a.x;
        top4i(p.a.y, __float_as_int(p.b.y), v0, i0, v1, i1, v2, i2, v3, i3);
        top4i(p.a.z, __float_as_int(p.b.z), v0, i0, v1, i1, v2, i2, v3, i3);
        top4i(p.a.w, __float_as_int(p.b.w), v0, i0, v1, i1, v2, i2, v3, i3);
        top4i(p.b.x, p.c.x,                 v0, i0, v1, i1, v2, i2, v3, i3);
    }
    #pragma unroll
    for (int d = 16; d > 0; d >>= 1) {
        S += __shfl_xor_sync(0xFFFFFFFFu, S, d);
        // snapshot all four before inserting (symmetric-merge hazard)
        float ov0 = __shfl_xor_sync(0xFFFFFFFFu, v0, d);
        float ov1 = __shfl_xor_sync(0xFFFFFFFFu, v1, d);
        float ov2 = __shfl_xor_sync(0xFFFFFFFFu, v2, d);
        float ov3 = __shfl_xor_sync(0xFFFFFFFFu, v3, d);
        int   oj0 = __shfl_xor_sync(0xFFFFFFFFu, i0, d);
        int   oj1 = __shfl_xor_sync(0xFFFFFFFFu, i1, d);
        int   oj2 = __shfl_xor_sync(0xFFFFFFFFu, i2, d);
        int   oj3 = __shfl_xor_sync(0xFFFFFFFFu, i3, d);
        top4i(ov0, oj0, v0, i0, v1, i1, v2, i2, v3, i3);
        top4i(ov1, oj1, v0, i0, v1, i1, v2, i2, v3, i3);
        top4i(ov2, oj2, v0, i0, v1, i1, v2, i2, v3, i3);
        top4i(ov3, oj3, v0, i0, v1, i1, v2, i2, v3, i3);
    }
    if (lane == 0) {
        float Sw = S + (expf(2.f * v0) - expf(v0)) + (expf(2.f * v1) - expf(v1))
                     + (expf(2.f * v2) - expf(v2)) + (expf(2.f * v3) - expf(v3));
        g_rowlse[row] = logf(Sw);
        g_hard_val[row * 4 + 0] = v0; g_hard_idx[row * 4 + 0] = i0;
        g_hard_val[row * 4 + 1] = v1; g_hard_idx[row * 4 + 1] = i1;
        g_hard_val[row * 4 + 2] = v2; g_hard_idx[row * 4 + 2] = i2;
        g_hard_val[row * 4 + 3] = v3; g_hard_idx[row * 4 + 3] = i3;
    }
}

// ---------------------------------------------------------------------------
// K3: per-column merge of 256 band sums; zero corr
// ---------------------------------------------------------------------------
__global__ __launch_bounds__(256) void colmerge_kernel()
{
    const int col = blockIdx.x * 256 + threadIdx.x;
    float s = 0.f;
    #pragma unroll 8
    for (int r = 0; r < NRSUB; r++) s += g_cp[r][col];
    g_cs[col] = s;
    g_corr[col] = 0;
}

// ---------------------------------------------------------------------------
// K3b: hard-negative column corrections (int64 fixed point, order-independent)
// ---------------------------------------------------------------------------
__global__ __launch_bounds__(256) void colfix_kernel()
{
    const int t = blockIdx.x * 256 + threadIdx.x;   // 0..32767
    float x = g_hard_val[t];
    int j = g_hard_idx[t];
    float delta = expf(2.0f * x) - expf(x);
    long long q = (long long)((double)delta * CORR_SCALE);
    atomicAdd((unsigned long long*)&g_corr[j], (unsigned long long)q);
}

// ---------------------------------------------------------------------------
// K4: loss = sum_i [(rowLSE_i - diag_i) + (colLSE_i - diag_i)] / (2B)
// ---------------------------------------------------------------------------
__global__ __launch_bounds__(256) void finalize_kernel(float* __restrict__ out)
{
    __shared__ float red[256];
    const int tid = threadIdx.x;
    float acc = 0.f;
    for (int i = tid; i < BATCH; i += 256) {
        float corr = (float)((double)g_corr[i] * (1.0 / CORR_SCALE));
        float collse = logf(g_cs[i] + corr);
        acc += (g_rowlse[i] - g_diag[i]) + (collse - g_diag[i]);
    }
    red[tid] = acc; __syncthreads();
    for (int s = 128; s > 0; s >>= 1) {
        if (tid < s) red[tid] += red[tid + s];
        __syncthreads();
    }
    if (tid == 0) out[0] = red[0] / (2.0f * (float)BATCH);
}

extern "C" void kernel_launch(void* const* d_in, const int* in_sizes, int n_in,
                              void* d_out, int out_size)
{
    (void)in_sizes; (void)n_in; (void)out_size;
    const float* V  = (const float*)d_in[0];   // vision_embed [8192, 256]
    const float* Tm = (const float*)d_in[1];   // text_embed   [8192, 256]
    float* out = (float*)d_out;

    cudaFuncSetAttribute(mma_gemm_kernel,
                         cudaFuncAttributeMaxDynamicSharedMemorySize, SMEM_TOTAL);

    split_kernel<<<(BATCH * DIM + 255) / 256, 256>>>(V, Tm);
    mma_gemm_kernel<<<dim3(BATCH / TN, BATCH / TM), 256, SMEM_TOTAL>>>();
    diag_kernel<<<BATCH / 8, 256>>>(V, Tm);
    rowmerge_kernel<<<BATCH / 8, 256>>>();
    colmerge_kernel<<<BATCH / 256, 256>>>();
    colfix_kernel<<<(BATCH * 4) / 256, 256>>>();
    finalize_kernel<<<1, 256>>>(out);
}

// round 8
// speedup vs baseline: 3.3720x; 1.8166x over previous
#include <cuda_runtime.h>
#include <cuda_fp16.h>
#include <math.h>
#include <stdint.h>

#define BATCH 8192
#define DIM 256

// GEMM tiling: CTA 128x128, 8 warps of 32x64, 2 CTAs/SM, K = 256 fp16
#define TM 128
#define TN 128
#define KC 32                         // fp16 per K stage
#define NCHUNK (DIM / KC)             // 8
#define ROWPITCH 80                   // bytes per smem row (32 fp16 = 64B, pad to 80)
#define STAGE_BYTES ((TM + TN) * ROWPITCH)   // 20480
#define NSTAGES 3
#define SMEM_TOTAL (STAGE_BYTES * NSTAGES)   // 61440

#define NCTILE (BATCH / 64)           // 128 column tiles of 64 (per-warp col range)
#define NRSUB  (BATCH / 32)           // 256 row bands of 32 (per-warp row range)

#define CORR_SCALE 524288.0           // 2^19 fixed-point for column corrections

// Row partial: sum + top4 (vals, idx). 48B.
struct __align__(16) RP { float4 a; float4 b; int4 c; };
// a = (sum, v0, v1, v2); b = (v3, bits(i0), bits(i1), bits(i2)); c.x = i3

// Scratch (device globals: allocation-free per harness rules)
static __device__ __half g_Ah[(size_t)BATCH * DIM];
static __device__ __half g_Bh[(size_t)BATCH * DIM];
static __device__ RP    g_rp[BATCH][NCTILE];          // 48 MB
static __device__ float g_cp[NRSUB][BATCH];           // 8 MB (plain col sums)
static __device__ float g_diag[BATCH];
static __device__ float g_rowlse[BATCH];
static __device__ float g_cs[BATCH];
static __device__ long long g_corr[BATCH];
static __device__ float g_hard_val[BATCH * 4];
static __device__ int   g_hard_idx[BATCH * 4];

// ---------------------------------------------------------------------------
// helpers
// ---------------------------------------------------------------------------
__device__ __forceinline__ uint32_t smem_to_u32(const void* p) {
    uint32_t a;
    asm("{ .reg .u64 t; cvta.to.shared.u64 t, %1; cvt.u32.u64 %0, t; }"
        : "=r"(a) : "l"(p));
    return a;
}
__device__ __forceinline__ void cp_async16(uint32_t smem_addr, const void* gptr) {
    asm volatile("cp.async.cg.shared.global [%0], [%1], 16;"
        :: "r"(smem_addr), "l"(gptr));
}
#define CP_COMMIT() asm volatile("cp.async.commit_group;" ::: "memory")
#define CP_WAIT1()  asm volatile("cp.async.wait_group 1;" ::: "memory")

__device__ __forceinline__ void ldsm_x4(uint32_t& r0, uint32_t& r1,
                                        uint32_t& r2, uint32_t& r3, uint32_t addr) {
    asm volatile("ldmatrix.sync.aligned.m8n8.x4.shared.b16 {%0,%1,%2,%3}, [%4];"
                 : "=r"(r0), "=r"(r1), "=r"(r2), "=r"(r3) : "r"(addr));
}
__device__ __forceinline__ void mma_f16(float* d, const uint32_t* a, const uint32_t* b) {
    asm volatile(
        "mma.sync.aligned.m16n8k16.row.col.f32.f16.f16.f32 "
        "{%0,%1,%2,%3}, {%4,%5,%6,%7}, {%8,%9}, {%0,%1,%2,%3};"
        : "+f"(d[0]), "+f"(d[1]), "+f"(d[2]), "+f"(d[3])
        : "r"(a[0]), "r"(a[1]), "r"(a[2]), "r"(a[3]), "r"(b[0]), "r"(b[1]));
}

// top-4 insert tracking (value, index), descending
__device__ __forceinline__ void top4i(float v, int i,
                                      float& v0, int& i0, float& v1, int& i1,
                                      float& v2, int& i2, float& v3, int& i3)
{
    if (v > v3) {
        if (v > v0)      { v3=v2;i3=i2; v2=v1;i2=i1; v1=v0;i1=i0; v0=v;i0=i; }
        else if (v > v1) { v3=v2;i3=i2; v2=v1;i2=i1; v1=v;i1=i; }
        else if (v > v2) { v3=v2;i3=i2; v2=v;i2=i; }
        else             { v3=v;i3=i; }
    }
}

// ---------------------------------------------------------------------------
// K0: fp16 convert (10 mantissa bits; dropped lo-terms give ~2e-4 logit std)
// ---------------------------------------------------------------------------
__global__ __launch_bounds__(256) void split_kernel(const float* __restrict__ V,
                                                    const float* __restrict__ Tm)
{
    size_t idx = (size_t)blockIdx.x * 256 + threadIdx.x;
    if (idx >= (size_t)BATCH * DIM) return;
    g_Ah[idx] = __float2half(V[idx]);
    g_Bh[idx] = __float2half(Tm[idx]);
}

// ---------------------------------------------------------------------------
// K1: fp16 HMMA GEMM (K=256), fused epilogue (row sum+top4, col sums).
// 128x128 CTA tile, 8 warps of 32x64, 3-stage cp.async, 2 CTAs/SM.
// ---------------------------------------------------------------------------
__global__ __launch_bounds__(256, 2) void mma_gemm_kernel()
{
    extern __shared__ char smem[];
    const uint32_t smem_base = smem_to_u32(smem);
    const int tid = threadIdx.x;
    const int wid = tid >> 5;
    const int lane = tid & 31;
    const int m0 = blockIdx.y * TM;
    const int n0 = blockIdx.x * TN;

    const int wm = (wid & 3) * 32;   // warp row offset in tile
    const int wn = (wid >> 2) * 64;  // warp col offset in tile

    const char* Ag = (const char*)g_Ah;
    const char* Bg = (const char*)g_Bh;

    // stage loader: A rows [m0,m0+128) then B rows [n0,n0+128), 16B chunks
    auto load_stage = [&](int s) {
        const uint32_t sb = smem_base + (uint32_t)(s % NSTAGES) * STAGE_BYTES;
        const int kelem = s * KC;
        #pragma unroll
        for (int j = 0; j < 4; j++) {
            int c = tid + j * 256;                 // 0..1023
            int row = c >> 2, q = c & 3;           // row 0..255, q 0..3
            if (row < TM) {
                cp_async16(sb + row * ROWPITCH + q * 16,
                           Ag + ((size_t)(m0 + row) * DIM + kelem + q * 8) * 2);
            } else {
                cp_async16(sb + row * ROWPITCH + q * 16,
                           Bg + ((size_t)(n0 + row - TM) * DIM + kelem + q * 8) * 2);
            }
        }
        CP_COMMIT();
    };

    float acc[2][8][4];
    #pragma unroll
    for (int mt = 0; mt < 2; mt++)
        #pragma unroll
        for (int nt = 0; nt < 8; nt++)
            #pragma unroll
            for (int e = 0; e < 4; e++) acc[mt][nt][e] = 0.f;

    load_stage(0);
    load_stage(1);

    for (int s = 0; s < NCHUNK; s++) {
        CP_WAIT1();
        __syncthreads();
        if (s + 2 < NCHUNK) load_stage(s + 2);

        const uint32_t sb = smem_base + (uint32_t)(s % NSTAGES) * STAGE_BYTES;
        const uint32_t Asb = sb;
        const uint32_t Bsb = sb + TM * ROWPITCH;

        #pragma unroll
        for (int ks = 0; ks < 2; ks++) {
            const int kb = ks * 32;
            uint32_t a[2][4], b[8][2];
            #pragma unroll
            for (int mt = 0; mt < 2; mt++) {
                uint32_t addr = Asb + (wm + mt * 16 + (lane & 15)) * ROWPITCH
                              + kb + (lane >> 4) * 16;
                ldsm_x4(a[mt][0], a[mt][1], a[mt][2], a[mt][3], addr);
            }
            #pragma unroll
            for (int np = 0; np < 4; np++) {
                int n = wn + np * 16 + (lane & 7) + ((lane >> 4) << 3);
                uint32_t addr = Bsb + n * ROWPITCH + kb + (((lane >> 3) & 1) << 4);
                ldsm_x4(b[np * 2][0], b[np * 2][1], b[np * 2 + 1][0], b[np * 2 + 1][1], addr);
            }
            #pragma unroll
            for (int mt = 0; mt < 2; mt++)
                #pragma unroll
                for (int nt = 0; nt < 8; nt++)
                    mma_f16(acc[mt][nt], a[mt], b[nt]);
        }
        __syncthreads();
    }

    // ======================= FUSED EPILOGUE =======================
    // row = m0+wm+mt*16+(lane>>2)+h*8; col = n0+wn+nt*8+(lane&3)*2+e;
    // value = acc[mt][nt][h*2+e]
    const float inv_t = 1.0f / 0.07f;
    const int lr = lane >> 2;
    const int lc = lane & 3;
    const int ctile = blockIdx.x * 2 + (wid >> 2);   // 64-col tile index
    const int rsub  = blockIdx.y * 4 + (wid & 3);    // 32-row band index

    float cs[16];
    #pragma unroll
    for (int c = 0; c < 16; c++) cs[c] = 0.f;

    #pragma unroll
    for (int mt = 0; mt < 2; mt++) {
        #pragma unroll
        for (int h = 0; h < 2; h++) {
            const int row = m0 + wm + mt * 16 + lr + h * 8;
            float rsum = 0.f;
            float v0 = -3e38f, v1 = -3e38f, v2 = -3e38f, v3 = -3e38f;
            int i0 = 0, i1 = 0, i2 = 0, i3 = 0;
            #pragma unroll
            for (int nt = 0; nt < 8; nt++) {
                #pragma unroll
                for (int e = 0; e < 2; e++) {
                    const int col = n0 + wn + nt * 8 + lc * 2 + e;
                    float x = acc[mt][nt][h * 2 + e] * inv_t;
                    float ex = __expf(x);
                    rsum += ex;
                    cs[nt * 2 + e] += ex;
                    if (col != row)
                        top4i(x, col, v0, i0, v1, i1, v2, i2, v3, i3);
                }
            }
            // reduce over lc (lane bits 0..1) — snapshot before inserting
            #pragma unroll
            for (int d = 1; d <= 2; d <<= 1) {
                rsum += __shfl_xor_sync(0xFFFFFFFFu, rsum, d);
                float ov0 = __shfl_xor_sync(0xFFFFFFFFu, v0, d);
                float ov1 = __shfl_xor_sync(0xFFFFFFFFu, v1, d);
                float ov2 = __shfl_xor_sync(0xFFFFFFFFu, v2, d);
                float ov3 = __shfl_xor_sync(0xFFFFFFFFu, v3, d);
                int   oj0 = __shfl_xor_sync(0xFFFFFFFFu, i0, d);
                int   oj1 = __shfl_xor_sync(0xFFFFFFFFu, i1, d);
                int   oj2 = __shfl_xor_sync(0xFFFFFFFFu, i2, d);
                int   oj3 = __shfl_xor_sync(0xFFFFFFFFu, i3, d);
                top4i(ov0, oj0, v0, i0, v1, i1, v2, i2, v3, i3);
                top4i(ov1, oj1, v0, i0, v1, i1, v2, i2, v3, i3);
                top4i(ov2, oj2, v0, i0, v1, i1, v2, i2, v3, i3);
                top4i(ov3, oj3, v0, i0, v1, i1, v2, i2, v3, i3);
            }
            if (lc == 0) {
                RP* p = &g_rp[row][ctile];
                p->a = make_float4(rsum, v0, v1, v2);
                p->b = make_float4(v3, __int_as_float(i0), __int_as_float(i1),
                                   __int_as_float(i2));
                p->c = make_int4(i3, 0, 0, 0);
            }
        }
    }

    // column sums: reduce over lr (lane bits 2..4)
    #pragma unroll
    for (int d = 4; d <= 16; d <<= 1) {
        #pragma unroll
        for (int c = 0; c < 16; c++)
            cs[c] += __shfl_xor_sync(0xFFFFFFFFu, cs[c], d);
    }
    if (lr == 0) {
        #pragma unroll
        for (int c = 0; c < 16; c++) {
            int col = n0 + wn + (c >> 1) * 8 + lc * 2 + (c & 1);
            g_cp[rsub][col] = cs[c];
        }
    }
}

// ---------------------------------------------------------------------------
// K1b: exact fp32 diag: diag_i = dot(V_i, T_i)/T.  One warp per row.
// ---------------------------------------------------------------------------
__global__ __launch_bounds__(256) void diag_kernel(const float* __restrict__ V,
                                                   const float* __restrict__ Tm)
{
    const int row = blockIdx.x * 8 + (threadIdx.x >> 5);
    const int lane = threadIdx.x & 31;
    const float4* v = (const float4*)(V + (size_t)row * DIM);
    const float4* t = (const float4*)(Tm + (size_t)row * DIM);
    float s = 0.f;
    #pragma unroll
    for (int q = 0; q < 2; q++) {
        float4 a = v[lane + q * 32];
        float4 b = t[lane + q * 32];
        s += a.x * b.x + a.y * b.y + a.z * b.z + a.w * b.w;
    }
    #pragma unroll
    for (int d = 16; d > 0; d >>= 1) s += __shfl_xor_sync(0xFFFFFFFFu, s, d);
    if (lane == 0) g_diag[row] = s * (1.0f / 0.07f);
}

// ---------------------------------------------------------------------------
// K2: per-row merge of 128 partials (one warp per row) -> weighted rowLSE
// ---------------------------------------------------------------------------
__global__ __launch_bounds__(256) void rowmerge_kernel()
{
    const int row = blockIdx.x * 8 + (threadIdx.x >> 5);
    const int lane = threadIdx.x & 31;

    float S = 0.f;
    float v0 = -3e38f, v1 = -3e38f, v2 = -3e38f, v3 = -3e38f;
    int i0 = 0, i1 = 0, i2 = 0, i3 = 0;
    #pragma unroll
    for (int q = 0; q < 4; q++) {
        RP p = g_rp[row][lane + q * 32];
        S += p.a.x;
        top4i(p.a.y, __float_as_int(p.b.y), v0, i0, v1, i1, v2, i2, v3, i3);
        top4i(p.a.z, __float_as_int(p.b.z), v0, i0, v1, i1, v2, i2, v3, i3);
        top4i(p.a.w, __float_as_int(p.b.w), v0, i0, v1, i1, v2, i2, v3, i3);
        top4i(p.b.x, p.c.x,                 v0, i0, v1, i1, v2, i2, v3, i3);
    }
    #pragma unroll
    for (int d = 16; d > 0; d >>= 1) {
        S += __shfl_xor_sync(0xFFFFFFFFu, S, d);
        // snapshot all four before inserting (symmetric-merge hazard)
        float ov0 = __shfl_xor_sync(0xFFFFFFFFu, v0, d);
        float ov1 = __shfl_xor_sync(0xFFFFFFFFu, v1, d);
        float ov2 = __shfl_xor_sync(0xFFFFFFFFu, v2, d);
        float ov3 = __shfl_xor_sync(0xFFFFFFFFu, v3, d);
        int   oj0 = __shfl_xor_sync(0xFFFFFFFFu, i0, d);
        int   oj1 = __shfl_xor_sync(0xFFFFFFFFu, i1, d);
        int   oj2 = __shfl_xor_sync(0xFFFFFFFFu, i2, d);
        int   oj3 = __shfl_xor_sync(0xFFFFFFFFu, i3, d);
        top4i(ov0, oj0, v0, i0, v1, i1, v2, i2, v3, i3);
        top4i(ov1, oj1, v0, i0, v1, i1, v2, i2, v3, i3);
        top4i(ov2, oj2, v0, i0, v1, i1, v2, i2, v3, i3);
        top4i(ov3, oj3, v0, i0, v1, i1, v2, i2, v3, i3);
    }
    if (lane == 0) {
        float Sw = S + (expf(2.f * v0) - expf(v0)) + (expf(2.f * v1) - expf(v1))
                     + (expf(2.f * v2) - expf(v2)) + (expf(2.f * v3) - expf(v3));
        g_rowlse[row] = logf(Sw);
        g_hard_val[row * 4 + 0] = v0; g_hard_idx[row * 4 + 0] = i0;
        g_hard_val[row * 4 + 1] = v1; g_hard_idx[row * 4 + 1] = i1;
        g_hard_val[row * 4 + 2] = v2; g_hard_idx[row * 4 + 2] = i2;
        g_hard_val[row * 4 + 3] = v3; g_hard_idx[row * 4 + 3] = i3;
    }
}

// ---------------------------------------------------------------------------
// K3: per-column merge of 256 band sums; zero corr
// ---------------------------------------------------------------------------
__global__ __launch_bounds__(256) void colmerge_kernel()
{
    const int col = blockIdx.x * 256 + threadIdx.x;
    float s = 0.f;
    #pragma unroll 8
    for (int r = 0; r < NRSUB; r++) s += g_cp[r][col];
    g_cs[col] = s;
    g_corr[col] = 0;
}

// ---------------------------------------------------------------------------
// K3b: hard-negative column corrections (int64 fixed point, order-independent)
// ---------------------------------------------------------------------------
__global__ __launch_bounds__(256) void colfix_kernel()
{
    const int t = blockIdx.x * 256 + threadIdx.x;   // 0..32767
    float x = g_hard_val[t];
    int j = g_hard_idx[t];
    float delta = expf(2.0f * x) - expf(x);
    long long q = (long long)((double)delta * CORR_SCALE);
    atomicAdd((unsigned long long*)&g_corr[j], (unsigned long long)q);
}

// ---------------------------------------------------------------------------
// K4: loss = sum_i [(rowLSE_i - diag_i) + (colLSE_i - diag_i)] / (2B)
// ---------------------------------------------------------------------------
__global__ __launch_bounds__(256) void finalize_kernel(float* __restrict__ out)
{
    __shared__ float red[256];
    const int tid = threadIdx.x;
    float acc = 0.f;
    for (int i = tid; i < BATCH; i += 256) {
        float corr = (float)((double)g_corr[i] * (1.0 / CORR_SCALE));
        float collse = logf(g_cs[i] + corr);
        acc += (g_rowlse[i] - g_diag[i]) + (collse - g_diag[i]);
    }
    red[tid] = acc; __syncthreads();
    for (int s = 128; s > 0; s >>= 1) {
        if (tid < s) red[tid] += red[tid + s];
        __syncthreads();
    }
    if (tid == 0) out[0] = red[0] / (2.0f * (float)BATCH);
}

extern "C" void kernel_launch(void* const* d_in, const int* in_sizes, int n_in,
                              void* d_out, int out_size)
{
    (void)in_sizes; (void)n_in; (void)out_size;
    const float* V  = (const float*)d_in[0];   // vision_embed [8192, 256]
    const float* Tm = (const float*)d_in[1];   // text_embed   [8192, 256]
    float* out = (float*)d_out;

    cudaFuncSetAttribute(mma_gemm_kernel,
                         cudaFuncAttributeMaxDynamicSharedMemorySize, SMEM_TOTAL);

    split_kernel<<<(BATCH * DIM + 255) / 256, 256>>>(V, Tm);
    mma_gemm_kernel<<<dim3(BATCH / TN, BATCH / TM), 256, SMEM_TOTAL>>>();
    diag_kernel<<<BATCH / 8, 256>>>(V, Tm);
    rowmerge_kernel<<<BATCH / 8, 256>>>();
    colmerge_kernel<<<BATCH / 256, 256>>>();
    colfix_kernel<<<(BATCH * 4) / 256, 256>>>();
    finalize_kernel<<<1, 256>>>(out);
}

// round 9
// speedup vs baseline: 3.5922x; 1.0653x over previous
#include <cuda_runtime.h>
#include <cuda_fp16.h>
#include <math.h>
#include <stdint.h>

#define BATCH 8192
#define DIM 256

// GEMM tiling: CTA 128x128, 8 warps of 32x64, 2 CTAs/SM, K = 256 fp16
#define TM 128
#define TN 128
#define KC 32                         // fp16 per K stage
#define NCHUNK (DIM / KC)             // 8
#define ROWPITCH 80                   // bytes per smem row (32 fp16 = 64B, pad to 80)
#define STAGE_BYTES ((TM + TN) * ROWPITCH)   // 20480
#define NSTAGES 3
#define SMEM_TOTAL (STAGE_BYTES * NSTAGES)   // 61440

#define NCTILE (BATCH / 64)           // 128 column tiles of 64 (per-warp col range)

#define CORR_SCALE 524288.0           // 2^19 fixed-point for atomic accumulators

// Row partial: top4 (vals, idx). 32B.
struct __align__(16) RP { float4 v; int4 i; };

// Scratch (device globals: allocation-free per harness rules)
static __device__ __half g_Ah[(size_t)BATCH * DIM];
static __device__ __half g_Bh[(size_t)BATCH * DIM];
static __device__ RP    g_rp[BATCH][NCTILE];          // 32 MB
static __device__ long long g_rowsum_fx[BATCH];       // fixed-point row sums
static __device__ long long g_colsum_fx[BATCH];       // fixed-point col sums (+hard corr)
static __device__ float g_diag[BATCH];
static __device__ float g_rowlse[BATCH];
static __device__ float g_hard_val[BATCH * 4];
static __device__ int   g_hard_idx[BATCH * 4];

// ---------------------------------------------------------------------------
// helpers
// ---------------------------------------------------------------------------
__device__ __forceinline__ uint32_t smem_to_u32(const void* p) {
    uint32_t a;
    asm("{ .reg .u64 t; cvta.to.shared.u64 t, %1; cvt.u32.u64 %0, t; }"
        : "=r"(a) : "l"(p));
    return a;
}
__device__ __forceinline__ void cp_async16(uint32_t smem_addr, const void* gptr) {
    asm volatile("cp.async.cg.shared.global [%0], [%1], 16;"
        :: "r"(smem_addr), "l"(gptr));
}
#define CP_COMMIT() asm volatile("cp.async.commit_group;" ::: "memory")
#define CP_WAIT1()  asm volatile("cp.async.wait_group 1;" ::: "memory")

__device__ __forceinline__ void ldsm_x4(uint32_t& r0, uint32_t& r1,
                                        uint32_t& r2, uint32_t& r3, uint32_t addr) {
    asm volatile("ldmatrix.sync.aligned.m8n8.x4.shared.b16 {%0,%1,%2,%3}, [%4];"
                 : "=r"(r0), "=r"(r1), "=r"(r2), "=r"(r3) : "r"(addr));
}
__device__ __forceinline__ void mma_f16(float* d, const uint32_t* a, const uint32_t* b) {
    asm volatile(
        "mma.sync.aligned.m16n8k16.row.col.f32.f16.f16.f32 "
        "{%0,%1,%2,%3}, {%4,%5,%6,%7}, {%8,%9}, {%0,%1,%2,%3};"
        : "+f"(d[0]), "+f"(d[1]), "+f"(d[2]), "+f"(d[3])
        : "r"(a[0]), "r"(a[1]), "r"(a[2]), "r"(a[3]), "r"(b[0]), "r"(b[1]));
}

// top-4 insert tracking (value, index), descending
__device__ __forceinline__ void top4i(float v, int i,
                                      float& v0, int& i0, float& v1, int& i1,
                                      float& v2, int& i2, float& v3, int& i3)
{
    if (v > v3) {
        if (v > v0)      { v3=v2;i3=i2; v2=v1;i2=i1; v1=v0;i1=i0; v0=v;i0=i; }
        else if (v > v1) { v3=v2;i3=i2; v2=v1;i2=i1; v1=v;i1=i; }
        else if (v > v2) { v3=v2;i3=i2; v2=v;i2=i; }
        else             { v3=v;i3=i; }
    }
}

__device__ __forceinline__ void atomic_add_fx(long long* addr, float val) {
    long long q = (long long)(val * (float)CORR_SCALE);
    atomicAdd((unsigned long long*)addr, (unsigned long long)q);
}

// ---------------------------------------------------------------------------
// K0: fp16 convert + zero the fixed-point accumulators (runs before GEMM)
// ---------------------------------------------------------------------------
__global__ __launch_bounds__(256) void split_kernel(const float* __restrict__ V,
                                                    const float* __restrict__ Tm)
{
    size_t idx = (size_t)blockIdx.x * 256 + threadIdx.x;
    if (idx >= (size_t)BATCH * DIM) return;
    g_Ah[idx] = __float2half(V[idx]);
    g_Bh[idx] = __float2half(Tm[idx]);
    if (idx < BATCH) {
        g_rowsum_fx[idx] = 0;
        g_colsum_fx[idx] = 0;
    }
}

// ---------------------------------------------------------------------------
// K1: fp16 HMMA GEMM (K=256), fused epilogue: row top4 -> g_rp,
// row/col sums -> fixed-point atomics. 128x128 CTA, 8 warps, 2 CTAs/SM.
// ---------------------------------------------------------------------------
__global__ __launch_bounds__(256, 2) void mma_gemm_kernel()
{
    extern __shared__ char smem[];
    const uint32_t smem_base = smem_to_u32(smem);
    const int tid = threadIdx.x;
    const int wid = tid >> 5;
    const int lane = tid & 31;
    const int m0 = blockIdx.y * TM;
    const int n0 = blockIdx.x * TN;

    const int wm = (wid & 3) * 32;   // warp row offset in tile
    const int wn = (wid >> 2) * 64;  // warp col offset in tile

    const char* Ag = (const char*)g_Ah;
    const char* Bg = (const char*)g_Bh;

    // stage loader: A rows [m0,m0+128) then B rows [n0,n0+128), 16B chunks
    auto load_stage = [&](int s) {
        const uint32_t sb = smem_base + (uint32_t)(s % NSTAGES) * STAGE_BYTES;
        const int kelem = s * KC;
        #pragma unroll
        for (int j = 0; j < 4; j++) {
            int c = tid + j * 256;                 // 0..1023
            int row = c >> 2, q = c & 3;           // row 0..255, q 0..3
            if (row < TM) {
                cp_async16(sb + row * ROWPITCH + q * 16,
                           Ag + ((size_t)(m0 + row) * DIM + kelem + q * 8) * 2);
            } else {
                cp_async16(sb + row * ROWPITCH + q * 16,
                           Bg + ((size_t)(n0 + row - TM) * DIM + kelem + q * 8) * 2);
            }
        }
        CP_COMMIT();
    };

    float acc[2][8][4];
    #pragma unroll
    for (int mt = 0; mt < 2; mt++)
        #pragma unroll
        for (int nt = 0; nt < 8; nt++)
            #pragma unroll
            for (int e = 0; e < 4; e++) acc[mt][nt][e] = 0.f;

    load_stage(0);
    load_stage(1);

    for (int s = 0; s < NCHUNK; s++) {
        CP_WAIT1();
        __syncthreads();
        if (s + 2 < NCHUNK) load_stage(s + 2);

        const uint32_t sb = smem_base + (uint32_t)(s % NSTAGES) * STAGE_BYTES;
        const uint32_t Asb = sb;
        const uint32_t Bsb = sb + TM * ROWPITCH;

        #pragma unroll
        for (int ks = 0; ks < 2; ks++) {
            const int kb = ks * 32;
            uint32_t a[2][4], b[8][2];
            #pragma unroll
            for (int mt = 0; mt < 2; mt++) {
                uint32_t addr = Asb + (wm + mt * 16 + (lane & 15)) * ROWPITCH
                              + kb + (lane >> 4) * 16;
                ldsm_x4(a[mt][0], a[mt][1], a[mt][2], a[mt][3], addr);
            }
            #pragma unroll
            for (int np = 0; np < 4; np++) {
                int n = wn + np * 16 + (lane & 7) + ((lane >> 4) << 3);
                uint32_t addr = Bsb + n * ROWPITCH + kb + (((lane >> 3) & 1) << 4);
                ldsm_x4(b[np * 2][0], b[np * 2][1], b[np * 2 + 1][0], b[np * 2 + 1][1], addr);
            }
            #pragma unroll
            for (int mt = 0; mt < 2; mt++)
                #pragma unroll
                for (int nt = 0; nt < 8; nt++)
                    mma_f16(acc[mt][nt], a[mt], b[nt]);
        }
        __syncthreads();
    }

    // ======================= FUSED EPILOGUE =======================
    // row = m0+wm+mt*16+(lane>>2)+h*8; col = n0+wn+nt*8+(lane&3)*2+e;
    // value = acc[mt][nt][h*2+e]
    const float inv_t = 1.0f / 0.07f;
    const int lr = lane >> 2;
    const int lc = lane & 3;
    const int ctile = blockIdx.x * 2 + (wid >> 2);   // 64-col tile index

    float cs[16];
    #pragma unroll
    for (int c = 0; c < 16; c++) cs[c] = 0.f;

    #pragma unroll
    for (int mt = 0; mt < 2; mt++) {
        #pragma unroll
        for (int h = 0; h < 2; h++) {
            const int row = m0 + wm + mt * 16 + lr + h * 8;
            float rsum = 0.f;
            float v0 = -3e38f, v1 = -3e38f, v2 = -3e38f, v3 = -3e38f;
            int i0 = 0, i1 = 0, i2 = 0, i3 = 0;
            #pragma unroll
            for (int nt = 0; nt < 8; nt++) {
                #pragma unroll
                for (int e = 0; e < 2; e++) {
                    const int col = n0 + wn + nt * 8 + lc * 2 + e;
                    float x = acc[mt][nt][h * 2 + e] * inv_t;
                    float ex = __expf(x);
                    rsum += ex;
                    cs[nt * 2 + e] += ex;
                    if (col != row)
                        top4i(x, col, v0, i0, v1, i1, v2, i2, v3, i3);
                }
            }
            // reduce over lc (lane bits 0..1) — snapshot before inserting
            #pragma unroll
            for (int d = 1; d <= 2; d <<= 1) {
                rsum += __shfl_xor_sync(0xFFFFFFFFu, rsum, d);
                float ov0 = __shfl_xor_sync(0xFFFFFFFFu, v0, d);
                float ov1 = __shfl_xor_sync(0xFFFFFFFFu, v1, d);
                float ov2 = __shfl_xor_sync(0xFFFFFFFFu, v2, d);
                float ov3 = __shfl_xor_sync(0xFFFFFFFFu, v3, d);
                int   oj0 = __shfl_xor_sync(0xFFFFFFFFu, i0, d);
                int   oj1 = __shfl_xor_sync(0xFFFFFFFFu, i1, d);
                int   oj2 = __shfl_xor_sync(0xFFFFFFFFu, i2, d);
                int   oj3 = __shfl_xor_sync(0xFFFFFFFFu, i3, d);
                top4i(ov0, oj0, v0, i0, v1, i1, v2, i2, v3, i3);
                top4i(ov1, oj1, v0, i0, v1, i1, v2, i2, v3, i3);
                top4i(ov2, oj2, v0, i0, v1, i1, v2, i2, v3, i3);
                top4i(ov3, oj3, v0, i0, v1, i1, v2, i2, v3, i3);
            }
            if (lc == 0) {
                RP* p = &g_rp[row][ctile];
                p->v = make_float4(v0, v1, v2, v3);
                p->i = make_int4(i0, i1, i2, i3);
                atomic_add_fx(&g_rowsum_fx[row], rsum);
            }
        }
    }

    // column sums: reduce over lr (lane bits 2..4), then fixed-point atomics
    #pragma unroll
    for (int d = 4; d <= 16; d <<= 1) {
        #pragma unroll
        for (int c = 0; c < 16; c++)
            cs[c] += __shfl_xor_sync(0xFFFFFFFFu, cs[c], d);
    }
    if (lr == 0) {
        #pragma unroll
        for (int c = 0; c < 16; c++) {
            int col = n0 + wn + (c >> 1) * 8 + lc * 2 + (c & 1);
            atomic_add_fx(&g_colsum_fx[col], cs[c]);
        }
    }
}

// ---------------------------------------------------------------------------
// K1b: exact fp32 diag: diag_i = dot(V_i, T_i)/T.  One warp per row.
// ---------------------------------------------------------------------------
__global__ __launch_bounds__(256) void diag_kernel(const float* __restrict__ V,
                                                   const float* __restrict__ Tm)
{
    const int row = blockIdx.x * 8 + (threadIdx.x >> 5);
    const int lane = threadIdx.x & 31;
    const float4* v = (const float4*)(V + (size_t)row * DIM);
    const float4* t = (const float4*)(Tm + (size_t)row * DIM);
    float s = 0.f;
    #pragma unroll
    for (int q = 0; q < 2; q++) {
        float4 a = v[lane + q * 32];
        float4 b = t[lane + q * 32];
        s += a.x * b.x + a.y * b.y + a.z * b.z + a.w * b.w;
    }
    #pragma unroll
    for (int d = 16; d > 0; d >>= 1) s += __shfl_xor_sync(0xFFFFFFFFu, s, d);
    if (lane == 0) g_diag[row] = s * (1.0f / 0.07f);
}

// ---------------------------------------------------------------------------
// K2: per-row merge of 128 top4 partials (one warp per row) -> weighted rowLSE
// ---------------------------------------------------------------------------
__global__ __launch_bounds__(256) void rowmerge_kernel()
{
    const int row = blockIdx.x * 8 + (threadIdx.x >> 5);
    const int lane = threadIdx.x & 31;

    float v0 = -3e38f, v1 = -3e38f, v2 = -3e38f, v3 = -3e38f;
    int i0 = 0, i1 = 0, i2 = 0, i3 = 0;
    #pragma unroll
    for (int q = 0; q < 4; q++) {
        RP p = g_rp[row][lane + q * 32];
        top4i(p.v.x, p.i.x, v0, i0, v1, i1, v2, i2, v3, i3);
        top4i(p.v.y, p.i.y, v0, i0, v1, i1, v2, i2, v3, i3);
        top4i(p.v.z, p.i.z, v0, i0, v1, i1, v2, i2, v3, i3);
        top4i(p.v.w, p.i.w, v0, i0, v1, i1, v2, i2, v3, i3);
    }
    #pragma unroll
    for (int d = 16; d > 0; d >>= 1) {
        // snapshot all four before inserting (symmetric-merge hazard)
        float ov0 = __shfl_xor_sync(0xFFFFFFFFu, v0, d);
        float ov1 = __shfl_xor_sync(0xFFFFFFFFu, v1, d);
        float ov2 = __shfl_xor_sync(0xFFFFFFFFu, v2, d);
        float ov3 = __shfl_xor_sync(0xFFFFFFFFu, v3, d);
        int   oj0 = __shfl_xor_sync(0xFFFFFFFFu, i0, d);
        int   oj1 = __shfl_xor_sync(0xFFFFFFFFu, i1, d);
        int   oj2 = __shfl_xor_sync(0xFFFFFFFFu, i2, d);
        int   oj3 = __shfl_xor_sync(0xFFFFFFFFu, i3, d);
        top4i(ov0, oj0, v0, i0, v1, i1, v2, i2, v3, i3);
        top4i(ov1, oj1, v0, i0, v1, i1, v2, i2, v3, i3);
        top4i(ov2, oj2, v0, i0, v1, i1, v2, i2, v3, i3);
        top4i(ov3, oj3, v0, i0, v1, i1, v2, i2, v3, i3);
    }
    if (lane == 0) {
        float S = (float)((double)g_rowsum_fx[row] * (1.0 / CORR_SCALE));
        float Sw = S + (expf(2.f * v0) - expf(v0)) + (expf(2.f * v1) - expf(v1))
                     + (expf(2.f * v2) - expf(v2)) + (expf(2.f * v3) - expf(v3));
        g_rowlse[row] = logf(Sw);
        g_hard_val[row * 4 + 0] = v0; g_hard_idx[row * 4 + 0] = i0;
        g_hard_val[row * 4 + 1] = v1; g_hard_idx[row * 4 + 1] = i1;
        g_hard_val[row * 4 + 2] = v2; g_hard_idx[row * 4 + 2] = i2;
        g_hard_val[row * 4 + 3] = v3; g_hard_idx[row * 4 + 3] = i3;
    }
}

// ---------------------------------------------------------------------------
// K3: hard-negative column corrections straight into the col accumulator
// ---------------------------------------------------------------------------
__global__ __launch_bounds__(256) void colfix_kernel()
{
    const int t = blockIdx.x * 256 + threadIdx.x;   // 0..32767
    float x = g_hard_val[t];
    int j = g_hard_idx[t];
    float delta = expf(2.0f * x) - expf(x);
    long long q = (long long)((double)delta * CORR_SCALE);
    atomicAdd((unsigned long long*)&g_colsum_fx[j], (unsigned long long)q);
}

// ---------------------------------------------------------------------------
// K4: loss = sum_i [(rowLSE_i - diag_i) + (colLSE_i - diag_i)] / (2B)
// ---------------------------------------------------------------------------
__global__ __launch_bounds__(256) void finalize_kernel(float* __restrict__ out)
{
    __shared__ float red[256];
    const int tid = threadIdx.x;
    float acc = 0.f;
    for (int i = tid; i < BATCH; i += 256) {
        float collse = logf((float)((double)g_colsum_fx[i] * (1.0 / CORR_SCALE)));
        acc += (g_rowlse[i] - g_diag[i]) + (collse - g_diag[i]);
    }
    red[tid] = acc; __syncthreads();
    for (int s = 128; s > 0; s >>= 1) {
        if (tid < s) red[tid] += red[tid + s];
        __syncthreads();
    }
    if (tid == 0) out[0] = red[0] / (2.0f * (float)BATCH);
}

extern "C" void kernel_launch(void* const* d_in, const int* in_sizes, int n_in,
                              void* d_out, int out_size)
{
    (void)in_sizes; (void)n_in; (void)out_size;
    const float* V  = (const float*)d_in[0];   // vision_embed [8192, 256]
    const float* Tm = (const float*)d_in[1];   // text_embed   [8192, 256]
    float* out = (float*)d_out;

    cudaFuncSetAttribute(mma_gemm_kernel,
                         cudaFuncAttributeMaxDynamicSharedMemorySize, SMEM_TOTAL);

    split_kernel<<<(BATCH * DIM + 255) / 256, 256>>>(V, Tm);
    mma_gemm_kernel<<<dim3(BATCH / TN, BATCH / TM), 256, SMEM_TOTAL>>>();
    diag_kernel<<<BATCH / 8, 256>>>(V, Tm);
    rowmerge_kernel<<<BATCH / 8, 256>>>();
    colfix_kernel<<<(BATCH * 4) / 256, 256>>>();
    finalize_kernel<<<1, 256>>>(out);
}

// round 11
// speedup vs baseline: 3.6761x; 1.0234x over previous
#include <cuda_runtime.h>
#include <cuda_fp16.h>
#include <math.h>
#include <stdint.h>

#define BATCH 8192
#define DIM 256

// GEMM tiling: CTA 128x128, 8 warps of 32x64, 2 CTAs/SM, K = 256 fp16
#define TM 128
#define TN 128
#define KC 64                         // fp16 per K stage
#define NCHUNK (DIM / KC)             // 4
#define ROWPITCH 144                  // 64 fp16 = 128B, pad to 144 (16B-aligned, conflict-free)
#define STAGE_BYTES ((TM + TN) * ROWPITCH)   // 36864
#define NSTAGES 3
#define SMEM_TOTAL (STAGE_BYTES * NSTAGES)   // 110592

#define NCTILE (BATCH / 64)           // 128 column tiles of 64 (per-warp col range)

#define CORR_SCALE 524288.0           // 2^19 fixed-point for atomic accumulators

// Row partial: top4 (vals, idx). 32B.
struct __align__(16) RP { float4 v; int4 i; };

// Scratch (device globals: allocation-free per harness rules)
static __device__ __half g_Ah[(size_t)BATCH * DIM];
static __device__ __half g_Bh[(size_t)BATCH * DIM];
static __device__ RP    g_rp[BATCH][NCTILE];          // 32 MB
static __device__ long long g_rowsum_fx[BATCH];       // fixed-point row sums
static __device__ long long g_colsum_fx[BATCH];       // fixed-point col sums (+hard corr)
static __device__ float g_diag[BATCH];
static __device__ float g_rowlse[BATCH];
static __device__ float g_hard_val[BATCH * 4];
static __device__ int   g_hard_idx[BATCH * 4];

// ---------------------------------------------------------------------------
// helpers
// ---------------------------------------------------------------------------
__device__ __forceinline__ uint32_t smem_to_u32(const void* p) {
    uint32_t a;
    asm("{ .reg .u64 t; cvta.to.shared.u64 t, %1; cvt.u32.u64 %0, t; }"
        : "=r"(a) : "l"(p));
    return a;
}
__device__ __forceinline__ void cp_async16(uint32_t smem_addr, const void* gptr) {
    asm volatile("cp.async.cg.shared.global [%0], [%1], 16;"
        :: "r"(smem_addr), "l"(gptr));
}
#define CP_COMMIT() asm volatile("cp.async.commit_group;" ::: "memory")
#define CP_WAIT1()  asm volatile("cp.async.wait_group 1;" ::: "memory")

__device__ __forceinline__ void ldsm_x4(uint32_t& r0, uint32_t& r1,
                                        uint32_t& r2, uint32_t& r3, uint32_t addr) {
    asm volatile("ldmatrix.sync.aligned.m8n8.x4.shared.b16 {%0,%1,%2,%3}, [%4];"
                 : "=r"(r0), "=r"(r1), "=r"(r2), "=r"(r3) : "r"(addr));
}
__device__ __forceinline__ void mma_f16(float* d, const uint32_t* a, const uint32_t* b) {
    asm volatile(
        "mma.sync.aligned.m16n8k16.row.col.f32.f16.f16.f32 "
        "{%0,%1,%2,%3}, {%4,%5,%6,%7}, {%8,%9}, {%0,%1,%2,%3};"
        : "+f"(d[0]), "+f"(d[1]), "+f"(d[2]), "+f"(d[3])
        : "r"(a[0]), "r"(a[1]), "r"(a[2]), "r"(a[3]), "r"(b[0]), "r"(b[1]));
}

// top-4 insert tracking (value, index), descending
__device__ __forceinline__ void top4i(float v, int i,
                                      float& v0, int& i0, float& v1, int& i1,
                                      float& v2, int& i2, float& v3, int& i3)
{
    if (v > v3) {
        if (v > v0)      { v3=v2;i3=i2; v2=v1;i2=i1; v1=v0;i1=i0; v0=v;i0=i; }
        else if (v > v1) { v3=v2;i3=i2; v2=v1;i2=i1; v1=v;i1=i; }
        else if (v > v2) { v3=v2;i3=i2; v2=v;i2=i; }
        else             { v3=v;i3=i; }
    }
}

__device__ __forceinline__ void atomic_add_fx(long long* addr, float val) {
    long long q = (long long)(val * (float)CORR_SCALE);
    atomicAdd((unsigned long long*)addr, (unsigned long long)q);
}

__device__ __forceinline__ uint32_t h2_bits(__half2 h) {
    return *reinterpret_cast<uint32_t*>(&h);
}

// ---------------------------------------------------------------------------
// K0: FUSED fp16 convert + exact fp32 diag + accumulator zeroing.
// One warp per row; inputs read exactly once.
// ---------------------------------------------------------------------------
__global__ __launch_bounds__(256) void convert_diag_kernel(const float* __restrict__ V,
                                                           const float* __restrict__ Tm)
{
    const int row = blockIdx.x * 8 + (threadIdx.x >> 5);
    const int lane = threadIdx.x & 31;

    const float4* v4 = (const float4*)(V + (size_t)row * DIM) + lane * 2;
    const float4* t4 = (const float4*)(Tm + (size_t)row * DIM) + lane * 2;
    float4 a0 = v4[0], a1 = v4[1];
    float4 b0 = t4[0], b1 = t4[1];

    uint4 ua, ub;
    ua.x = h2_bits(__floats2half2_rn(a0.x, a0.y));
    ua.y = h2_bits(__floats2half2_rn(a0.z, a0.w));
    ua.z = h2_bits(__floats2half2_rn(a1.x, a1.y));
    ua.w = h2_bits(__floats2half2_rn(a1.z, a1.w));
    ub.x = h2_bits(__floats2half2_rn(b0.x, b0.y));
    ub.y = h2_bits(__floats2half2_rn(b0.z, b0.w));
    ub.z = h2_bits(__floats2half2_rn(b1.x, b1.y));
    ub.w = h2_bits(__floats2half2_rn(b1.z, b1.w));
    *((uint4*)(g_Ah + (size_t)row * DIM) + lane) = ua;
    *((uint4*)(g_Bh + (size_t)row * DIM) + lane) = ub;

    float s = a0.x * b0.x + a0.y * b0.y + a0.z * b0.z + a0.w * b0.w
            + a1.x * b1.x + a1.y * b1.y + a1.z * b1.z + a1.w * b1.w;
    #pragma unroll
    for (int d = 16; d > 0; d >>= 1) s += __shfl_xor_sync(0xFFFFFFFFu, s, d);
    if (lane == 0) {
        g_diag[row] = s * (1.0f / 0.07f);
        g_rowsum_fx[row] = 0;
        g_colsum_fx[row] = 0;
    }
}

// ---------------------------------------------------------------------------
// K1: fp16 HMMA GEMM (K=256, KC=64), fused epilogue: row top4 -> g_rp,
// row/col sums -> fixed-point atomics. 128x128 CTA, 8 warps, 2 CTAs/SM.
// ---------------------------------------------------------------------------
__global__ __launch_bounds__(256, 2) void mma_gemm_kernel()
{
    extern __shared__ char smem[];
    const uint32_t smem_base = smem_to_u32(smem);
    const int tid = threadIdx.x;
    const int wid = tid >> 5;
    const int lane = tid & 31;
    const int m0 = blockIdx.y * TM;
    const int n0 = blockIdx.x * TN;

    const int wm = (wid & 3) * 32;   // warp row offset in tile
    const int wn = (wid >> 2) * 64;  // warp col offset in tile

    const char* Ag = (const char*)g_Ah;
    const char* Bg = (const char*)g_Bh;

    // stage loader: A rows [m0,m0+128) then B rows [n0,n0+128), 16B chunks
    auto load_stage = [&](int s) {
        const uint32_t sb = smem_base + (uint32_t)(s % NSTAGES) * STAGE_BYTES;
        const int kelem = s * KC;
        #pragma unroll
        for (int j = 0; j < 8; j++) {
            int c = tid + j * 256;                 // 0..2047
            int row = c >> 3, q = c & 7;           // row 0..255, q 0..7
            if (row < TM) {
                cp_async16(sb + row * ROWPITCH + q * 16,
                           Ag + ((size_t)(m0 + row) * DIM + kelem + q * 8) * 2);
            } else {
                cp_async16(sb + row * ROWPITCH + q * 16,
                           Bg + ((size_t)(n0 + row - TM) * DIM + kelem + q * 8) * 2);
            }
        }
        CP_COMMIT();
    };

    float acc[2][8][4];
    #pragma unroll
    for (int mt = 0; mt < 2; mt++)
        #pragma unroll
        for (int nt = 0; nt < 8; nt++)
            #pragma unroll
            for (int e = 0; e < 4; e++) acc[mt][nt][e] = 0.f;

    load_stage(0);
    load_stage(1);

    for (int s = 0; s < NCHUNK; s++) {
        CP_WAIT1();
        __syncthreads();
        if (s + 2 < NCHUNK) load_stage(s + 2);

        const uint32_t sb = smem_base + (uint32_t)(s % NSTAGES) * STAGE_BYTES;
        const uint32_t Asb = sb;
        const uint32_t Bsb = sb + TM * ROWPITCH;

        #pragma unroll
        for (int ks = 0; ks < 4; ks++) {
            const int kb = ks * 32;
            uint32_t a[2][4], b[8][2];
            #pragma unroll
            for (int mt = 0; mt < 2; mt++) {
                uint32_t addr = Asb + (wm + mt * 16 + (lane & 15)) * ROWPITCH
                              + kb + (lane >> 4) * 16;
                ldsm_x4(a[mt][0], a[mt][1], a[mt][2], a[mt][3], addr);
            }
            #pragma unroll
            for (int np = 0; np < 4; np++) {
                int n = wn + np * 16 + (lane & 7) + ((lane >> 4) << 3);
                uint32_t addr = Bsb + n * ROWPITCH + kb + (((lane >> 3) & 1) << 4);
                ldsm_x4(b[np * 2][0], b[np * 2][1], b[np * 2 + 1][0], b[np * 2 + 1][1], addr);
            }
            #pragma unroll
            for (int mt = 0; mt < 2; mt++)
                #pragma unroll
                for (int nt = 0; nt < 8; nt++)
                    mma_f16(acc[mt][nt], a[mt], b[nt]);
        }
        __syncthreads();
    }

    // ======================= FUSED EPILOGUE =======================
    // row = m0+wm+mt*16+(lane>>2)+h*8; col = n0+wn+nt*8+(lane&3)*2+e;
    // value = acc[mt][nt][h*2+e]
    const float inv_t = 1.0f / 0.07f;
    const int lr = lane >> 2;
    const int lc = lane & 3;
    const int ctile = blockIdx.x * 2 + (wid >> 2);   // 64-col tile index

    float cs[16];
    #pragma unroll
    for (int c = 0; c < 16; c++) cs[c] = 0.f;

    #pragma unroll
    for (int mt = 0; mt < 2; mt++) {
        #pragma unroll
        for (int h = 0; h < 2; h++) {
            const int row = m0 + wm + mt * 16 + lr + h * 8;
            float rsum = 0.f;
            float v0 = -3e38f, v1 = -3e38f, v2 = -3e38f, v3 = -3e38f;
            int i0 = 0, i1 = 0, i2 = 0, i3 = 0;
            #pragma unroll
            for (int nt = 0; nt < 8; nt++) {
                #pragma unroll
                for (int e = 0; e < 2; e++) {
                    const int col = n0 + wn + nt * 8 + lc * 2 + e;
                    float x = acc[mt][nt][h * 2 + e] * inv_t;
                    float ex = __expf(x);
                    rsum += ex;
                    cs[nt * 2 + e] += ex;
                    if (col != row)
                        top4i(x, col, v0, i0, v1, i1, v2, i2, v3, i3);
                }
            }
            // reduce over lc (lane bits 0..1) — snapshot before inserting
            #pragma unroll
            for (int d = 1; d <= 2; d <<= 1) {
                rsum += __shfl_xor_sync(0xFFFFFFFFu, rsum, d);
                float ov0 = __shfl_xor_sync(0xFFFFFFFFu, v0, d);
                float ov1 = __shfl_xor_sync(0xFFFFFFFFu, v1, d);
                float ov2 = __shfl_xor_sync(0xFFFFFFFFu, v2, d);
                float ov3 = __shfl_xor_sync(0xFFFFFFFFu, v3, d);
                int   oj0 = __shfl_xor_sync(0xFFFFFFFFu, i0, d);
                int   oj1 = __shfl_xor_sync(0xFFFFFFFFu, i1, d);
                int   oj2 = __shfl_xor_sync(0xFFFFFFFFu, i2, d);
                int   oj3 = __shfl_xor_sync(0xFFFFFFFFu, i3, d);
                top4i(ov0, oj0, v0, i0, v1, i1, v2, i2, v3, i3);
                top4i(ov1, oj1, v0, i0, v1, i1, v2, i2, v3, i3);
                top4i(ov2, oj2, v0, i0, v1, i1, v2, i2, v3, i3);
                top4i(ov3, oj3, v0, i0, v1, i1, v2, i2, v3, i3);
            }
            if (lc == 0) {
                RP* p = &g_rp[row][ctile];
                p->v = make_float4(v0, v1, v2, v3);
                p->i = make_int4(i0, i1, i2, i3);
                atomic_add_fx(&g_rowsum_fx[row], rsum);
            }
        }
    }

    // column sums: reduce over lr (lane bits 2..4), then fixed-point atomics
    #pragma unroll
    for (int d = 4; d <= 16; d <<= 1) {
        #pragma unroll
        for (int c = 0; c < 16; c++)
            cs[c] += __shfl_xor_sync(0xFFFFFFFFu, cs[c], d);
    }
    if (lr == 0) {
        #pragma unroll
        for (int c = 0; c < 16; c++) {
            int col = n0 + wn + (c >> 1) * 8 + lc * 2 + (c & 1);
            atomic_add_fx(&g_colsum_fx[col], cs[c]);
        }
    }
}

// ---------------------------------------------------------------------------
// K2: per-row merge of 128 top4 partials (one warp per row) -> weighted rowLSE
// ---------------------------------------------------------------------------
__global__ __launch_bounds__(256) void rowmerge_kernel()
{
    const int row = blockIdx.x * 8 + (threadIdx.x >> 5);
    const int lane = threadIdx.x & 31;

    float v0 = -3e38f, v1 = -3e38f, v2 = -3e38f, v3 = -3e38f;
    int i0 = 0, i1 = 0, i2 = 0, i3 = 0;
    #pragma unroll
    for (int q = 0; q < 4; q++) {
        RP p = g_rp[row][lane + q * 32];
        top4i(p.v.x, p.i.x, v0, i0, v1, i1, v2, i2, v3, i3);
        top4i(p.v.y, p.i.y, v0, i0, v1, i1, v2, i2, v3, i3);
        top4i(p.v.z, p.i.z, v0, i0, v1, i1, v2, i2, v3, i3);
        top4i(p.v.w, p.i.w, v0, i0, v1, i1, v2, i2, v3, i3);
    }
    #pragma unroll
    for (int d = 16; d > 0; d >>= 1) {
        // snapshot all four before inserting (symmetric-merge hazard)
        float ov0 = __shfl_xor_sync(0xFFFFFFFFu, v0, d);
        float ov1 = __shfl_xor_sync(0xFFFFFFFFu, v1, d);
        float ov2 = __shfl_xor_sync(0xFFFFFFFFu, v2, d);
        float ov3 = __shfl_xor_sync(0xFFFFFFFFu, v3, d);
        int   oj0 = __shfl_xor_sync(0xFFFFFFFFu, i0, d);
        int   oj1 = __shfl_xor_sync(0xFFFFFFFFu, i1, d);
        int   oj2 = __shfl_xor_sync(0xFFFFFFFFu, i2, d);
        int   oj3 = __shfl_xor_sync(0xFFFFFFFFu, i3, d);
        top4i(ov0, oj0, v0, i0, v1, i1, v2, i2, v3, i3);
        top4i(ov1, oj1, v0, i0, v1, i1, v2, i2, v3, i3);
        top4i(ov2, oj2, v0, i0, v1, i1, v2, i2, v3, i3);
        top4i(ov3, oj3, v0, i0, v1, i1, v2, i2, v3, i3);
    }
    if (lane == 0) {
        float S = (float)((double)g_rowsum_fx[row] * (1.0 / CORR_SCALE));
        float Sw = S + (expf(2.f * v0) - expf(v0)) + (expf(2.f * v1) - expf(v1))
                     + (expf(2.f * v2) - expf(v2)) + (expf(2.f * v3) - expf(v3));
        g_rowlse[row] = logf(Sw);
        g_hard_val[row * 4 + 0] = v0; g_hard_idx[row * 4 + 0] = i0;
        g_hard_val[row * 4 + 1] = v1; g_hard_idx[row * 4 + 1] = i1;
        g_hard_val[row * 4 + 2] = v2; g_hard_idx[row * 4 + 2] = i2;
        g_hard_val[row * 4 + 3] = v3; g_hard_idx[row * 4 + 3] = i3;
    }
}

// ---------------------------------------------------------------------------
// K3: hard-negative column corrections straight into the col accumulator
// ---------------------------------------------------------------------------
__global__ __launch_bounds__(256) void colfix_kernel()
{
    const int t = blockIdx.x * 256 + threadIdx.x;   // 0..32767
    float x = g_hard_val[t];
    int j = g_hard_idx[t];
    float delta = expf(2.0f * x) - expf(x);
    long long q = (long long)((double)delta * CORR_SCALE);
    atomicAdd((unsigned long long*)&g_colsum_fx[j], (unsigned long long)q);
}

// ---------------------------------------------------------------------------
// K4: loss = sum_i [(rowLSE_i - diag_i) + (colLSE_i - diag_i)] / (2B)
// ---------------------------------------------------------------------------
__global__ __launch_bounds__(256) void finalize_kernel(float* __restrict__ out)
{
    __shared__ float red[256];
    const int tid = threadIdx.x;
    float acc = 0.f;
    for (int i = tid; i < BATCH; i += 256) {
        float collse = logf((float)((double)g_colsum_fx[i] * (1.0 / CORR_SCALE)));
        acc += (g_rowlse[i] - g_diag[i]) + (collse - g_diag[i]);
    }
    red[tid] = acc; __syncthreads();
    for (int s = 128; s > 0; s >>= 1) {
        if (tid < s) red[tid] += red[tid + s];
        __syncthreads();
    }
    if (tid == 0) out[0] = red[0] / (2.0f * (float)BATCH);
}

extern "C" void kernel_launch(void* const* d_in, const int* in_sizes, int n_in,
                              void* d_out, int out_size)
{
    (void)in_sizes; (void)n_in; (void)out_size;
    const float* V  = (const float*)d_in[0];   // vision_embed [8192, 256]
    const float* Tm = (const float*)d_in[1];   // text_embed   [8192, 256]
    float* out = (float*)d_out;

    cudaFuncSetAttribute(mma_gemm_kernel,
                         cudaFuncAttributeMaxDynamicSharedMemorySize, SMEM_TOTAL);

    convert_diag_kernel<<<BATCH / 8, 256>>>(V, Tm);
    mma_gemm_kernel<<<dim3(BATCH / TN, BATCH / TM), 256, SMEM_TOTAL>>>();
    rowmerge_kernel<<<BATCH / 8, 256>>>();
    colfix_kernel<<<(BATCH * 4) / 256, 256>>>();
    finalize_kernel<<<1, 256>>>(out);
}